// round 14
// baseline (speedup 1.0000x reference)
#include <cuda_runtime.h>
#include <cuda_fp16.h>
#include <cstdint>
#include <cstddef>

#define B_  2
#define S_  2048
#define H_  1024
#define NH_ 16
#define HD_ 64
#define M_  (B_ * S_)   // 4096 rows

// Scratch (allocation-free rule: __device__ globals)
// Qh/Kh: hd-dim pi-permuted within 16-blocks (old pair (2q,2q+1)->pos 4q,
// old pair (2q+8,2q+9)->pos 4q+2). Vt: s-dim pi-permuted the same way.
__device__ __align__(16) __half g_INh[(size_t)3 * M_ * H_];            // q,k,v inputs fp16
__device__ __align__(16) __half g_Wh[(size_t)4 * H_ * H_];             // Wq,Wk,Wv,Wo fp16
__device__ __align__(16) __half g_Qh[(size_t)M_ * H_];                 // [b][s][h] fp16 (hd pi)
__device__ __align__(16) __half g_Kh[(size_t)M_ * H_];                 // [b][s][h] fp16 (hd pi)
__device__ __align__(16) __half g_Vt[(size_t)B_ * NH_ * HD_ * S_];     // [b][h][hd][s] fp16 (s pi)
__device__ __align__(16) __half g_AOh[(size_t)M_ * H_];                // attn out fp16 (natural)
__device__ __align__(16) __half g_FMh[(size_t)B_ * S_ * S_];           // -1 or sm*0.125 (fp16)

// ---------------------------------------------------------------------------
__device__ __forceinline__ uint32_t packh2(float lo, float hi) {
    uint32_t d;
    asm("cvt.rn.f16x2.f32 %0, %1, %2;" : "=r"(d) : "f"(hi), "f"(lo));
    return d;
}
__device__ __forceinline__ uint32_t ex2_h2(uint32_t t) {
    uint32_t d;
    asm("ex2.approx.f16x2 %0, %1;" : "=r"(d) : "r"(t));
    return d;
}

__device__ __forceinline__ void mma_f16(float& d0, float& d1, float& d2, float& d3,
                                        uint32_t a0, uint32_t a1, uint32_t a2, uint32_t a3,
                                        uint32_t b0, uint32_t b1) {
    asm volatile(
        "mma.sync.aligned.m16n8k16.row.col.f32.f16.f16.f32 "
        "{%0,%1,%2,%3}, {%4,%5,%6,%7}, {%8,%9}, {%0,%1,%2,%3};"
        : "+f"(d0), "+f"(d1), "+f"(d2), "+f"(d3)
        : "r"(a0), "r"(a1), "r"(a2), "r"(a3), "r"(b0), "r"(b1));
}

__device__ __forceinline__ uint32_t smem_u32(const void* p) {
    uint32_t a;
    asm("{ .reg .u64 t; cvta.to.shared.u64 t, %1; cvt.u32.u64 %0, t; }"
        : "=r"(a) : "l"(p));
    return a;
}
__device__ __forceinline__ void cp_async16(uint32_t dst, const void* src) {
    asm volatile("cp.async.cg.shared.global [%0], [%1], 16;"
                 :: "r"(dst), "l"(src) : "memory");
}
__device__ __forceinline__ void cp_commit() {
    asm volatile("cp.async.commit_group;" ::: "memory");
}
template <int N>
__device__ __forceinline__ void cp_wait() {
    asm volatile("cp.async.wait_group %0;" :: "n"(N) : "memory");
}

// ===========================================================================
// Convert inputs + weights to fp16 (once). Natural order (GEMM is un-pi'd).
// ===========================================================================
__global__ __launch_bounds__(256)
void cvt_kernel(const float* __restrict__ q, const float* __restrict__ k,
                const float* __restrict__ v,
                const float* __restrict__ wq, const float* __restrict__ wk,
                const float* __restrict__ wv, const float* __restrict__ wo,
                __half* __restrict__ inh, __half* __restrict__ wh)
{
    const int z = blockIdx.y;
    const int i = blockIdx.x * 256 + threadIdx.x;   // float4 index
    const float* src;
    __half* dst;
    int n;
    if (z < 3) {
        src = (z == 0) ? q : (z == 1) ? k : v;
        dst = inh + (size_t)z * M_ * H_;
        n = M_ * H_ / 4;
    } else {
        int w = z - 3;
        src = (w == 0) ? wq : (w == 1) ? wk : (w == 2) ? wv : wo;
        dst = wh + (size_t)w * H_ * H_;
        n = H_ * H_ / 4;
    }
    if (i < n) {
        float4 f = ((const float4*)src)[i];
        uint2 o;
        o.x = packh2(f.x, f.y);
        o.y = packh2(f.z, f.w);
        ((uint2*)dst)[i] = o;
    }
}

// ===========================================================================
// Fused mask (fp16): fm = (mask==0) ? -1 : script_mask * 0.125
// ===========================================================================
__global__ __launch_bounds__(256)
void fuse_mask_kernel(const int* __restrict__ mask, const float* __restrict__ sm,
                      __half* __restrict__ fm)
{
    int i = blockIdx.x * 256 + threadIdx.x;
    int4   m = ((const int4*)mask)[i];
    float4 s = ((const float4*)sm)[i];
    float o0 = (m.x == 0) ? -1.0f : s.x * 0.125f;
    float o1 = (m.y == 0) ? -1.0f : s.y * 0.125f;
    float o2 = (m.z == 0) ? -1.0f : s.z * 0.125f;
    float o3 = (m.w == 0) ? -1.0f : s.w * 0.125f;
    uint2 o;
    o.x = packh2(o0, o1);
    o.y = packh2(o2, o3);
    ((uint2*)fm)[i] = o;
}

// ===========================================================================
// fp16 GEMM core (R10-proven, unchanged): acc = X @ W^T. CTA 128x128,
// warp 64x32, K chunk 32, 3-stage cp.async, ONE barrier per chunk, RS=40.
// ===========================================================================
#define RS 40
#define G_STAGE_HALVES (2 * 128 * RS)              // A + B, one stage = 10240
#define G_SMEM_BYTES   (3 * G_STAGE_HALVES * 2)    // 61440
#define G_NCHUNK (H_ / 32)                          // 32

struct GemmCtx {
    int warp_m, warp_n, qrow, qcol, m0, n0;
    float acc[16][4];
};

__device__ __forceinline__ void gemm_compute(
    GemmCtx& g, const __half* __restrict__ X, const __half* __restrict__ W)
{
    extern __shared__ __half gsh[];
    const uint32_t sb = smem_u32(gsh);

    const int tid  = threadIdx.x;
    const int wid  = tid >> 5;
    const int lane = tid & 31;
    g.m0 = blockIdx.y * 128;
    g.n0 = blockIdx.x * 128;
    g.warp_m = (wid & 1) * 64;
    g.warp_n = (wid >> 1) * 32;
    g.qrow = lane >> 2;
    g.qcol = lane & 3;

    const int r0 = tid >> 1;            // 0..127
    const int h0 = (tid & 1) * 16;      // half-offset base in row

    const __half* Xa = X + (size_t)(g.m0 + r0) * H_ + h0;
    const __half* Wb = W + (size_t)(g.n0 + r0) * H_ + h0;
    const uint32_t da = sb + (uint32_t)(r0 * RS + h0) * 2;
    const uint32_t db = da + (uint32_t)(128 * RS) * 2;

    auto issue = [&](int c) {
        const uint32_t so = (uint32_t)((c % 3) * G_STAGE_HALVES) * 2;
        const int k0 = c * 32;
        cp_async16(da + so,      Xa + k0);
        cp_async16(da + so + 16, Xa + k0 + 8);
        cp_async16(db + so,      Wb + k0);
        cp_async16(db + so + 16, Wb + k0 + 8);
        cp_commit();
    };

#pragma unroll
    for (int i = 0; i < 16; ++i)
#pragma unroll
        for (int j = 0; j < 4; ++j) g.acc[i][j] = 0.0f;

    issue(0);
    issue(1);

    for (int c = 0; c < G_NCHUNK; ++c) {
        cp_wait<1>();
        __syncthreads();
        if (c + 2 < G_NCHUNK) issue(c + 2);
        else cp_commit();

        const __half* As = gsh + (c % 3) * G_STAGE_HALVES;
        const __half* Bs = As + 128 * RS;

#pragma unroll
        for (int ks = 0; ks < 2; ++ks) {
            const int kk = ks * 16 + 2 * g.qcol;
            uint32_t af[4][4];
            uint32_t bf[4][2];
#pragma unroll
            for (int mt = 0; mt < 4; ++mt) {
                const __half* ap = As + (g.warp_m + mt * 16 + g.qrow) * RS + kk;
                af[mt][0] = *(const uint32_t*)ap;
                af[mt][1] = *(const uint32_t*)(ap + 8 * RS);
                af[mt][2] = *(const uint32_t*)(ap + 8);
                af[mt][3] = *(const uint32_t*)(ap + 8 * RS + 8);
            }
#pragma unroll
            for (int nt = 0; nt < 4; ++nt) {
                const __half* bp = Bs + (g.warp_n + nt * 8 + g.qrow) * RS + kk;
                bf[nt][0] = *(const uint32_t*)bp;
                bf[nt][1] = *(const uint32_t*)(bp + 8);
            }
#pragma unroll
            for (int mt = 0; mt < 4; ++mt)
#pragma unroll
                for (int nt = 0; nt < 4; ++nt)
                    mma_f16(g.acc[mt * 4 + nt][0], g.acc[mt * 4 + nt][1],
                            g.acc[mt * 4 + nt][2], g.acc[mt * 4 + nt][3],
                            af[mt][0], af[mt][1], af[mt][2], af[mt][3],
                            bf[nt][0], bf[nt][1]);
        }
    }
}

// Fused Q/K/V projections. z=0/1 -> fp16 [b][s][h] pi-store (hd);
// z=2 -> fp16 V^T store with pi-permuted s.
__global__ __launch_bounds__(256, 2)
void qkv_gemm_kernel(const __half* __restrict__ inh, const __half* __restrict__ wh,
                     const float* __restrict__ bq, const float* __restrict__ bk,
                     const float* __restrict__ bv,
                     __half* __restrict__ Cq, __half* __restrict__ Ck,
                     __half* __restrict__ Cvt)
{
    const int z = blockIdx.z;
    const __half* X = inh + (size_t)z * M_ * H_;
    const __half* W = wh + (size_t)z * H_ * H_;
    const float* bias = (z == 0) ? bq : (z == 1) ? bk : bv;

    GemmCtx g;
    gemm_compute(g, X, W);

    if (z < 2) {
        __half* C = (z == 0) ? Cq : Ck;
#pragma unroll
        for (int mt = 0; mt < 4; ++mt) {
            int row = g.m0 + g.warp_m + mt * 16 + g.qrow;
#pragma unroll
            for (int nt = 0; nt < 4; ++nt) {
                int col = g.n0 + g.warp_n + nt * 8 + 2 * g.qcol;   // natural col
                int ncol = (col & ~15) + 4 * g.qcol + ((nt & 1) << 1);
                float b0v = __ldg(&bias[col]);
                float b1v = __ldg(&bias[col + 1]);
                uint32_t h0v = packh2(g.acc[mt * 4 + nt][0] + b0v,
                                      g.acc[mt * 4 + nt][1] + b1v);
                uint32_t h1v = packh2(g.acc[mt * 4 + nt][2] + b0v,
                                      g.acc[mt * 4 + nt][3] + b1v);
                *(uint32_t*)(C + (size_t)row * H_ + ncol)       = h0v;
                *(uint32_t*)(C + (size_t)(row + 8) * H_ + ncol) = h1v;
            }
        }
    } else {
        // V transposed: [b][h][hd][s], s pi-permuted within 16-blocks
#pragma unroll
        for (int mt = 0; mt < 4; ++mt) {
            int srow = g.m0 + g.warp_m + mt * 16 + g.qrow;
            int bb = srow >> 11, s = srow & 2047;
            int j = s & 15;                       // 0..7 here (qrow 0..7)
            int pos0 = (s & ~15) + 4 * (j >> 1) + (j & 1);   // old row j
#pragma unroll
            for (int nt = 0; nt < 4; ++nt) {
                int col = g.n0 + g.warp_n + nt * 8 + 2 * g.qcol;
                float b0v = __ldg(&bias[col]);
                float b1v = __ldg(&bias[col + 1]);
                int hh = col >> 6, hd = col & 63;
                __half* p = Cvt + ((size_t)(bb * NH_ + hh) * HD_ + hd) * S_;
                p[pos0]          = __float2half_rn(g.acc[mt * 4 + nt][0] + b0v);
                p[S_ + pos0]     = __float2half_rn(g.acc[mt * 4 + nt][1] + b1v);
                p[pos0 + 2]      = __float2half_rn(g.acc[mt * 4 + nt][2] + b0v);
                p[S_ + pos0 + 2] = __float2half_rn(g.acc[mt * 4 + nt][3] + b1v);
            }
        }
    }
}

__global__ __launch_bounds__(256, 2)
void out_gemm_kernel(const __half* __restrict__ X, const __half* __restrict__ wh,
                     const float* __restrict__ bias, float* __restrict__ C)
{
    GemmCtx g;
    gemm_compute(g, X, wh + (size_t)3 * H_ * H_);
#pragma unroll
    for (int mt = 0; mt < 4; ++mt) {
        int row = g.m0 + g.warp_m + mt * 16 + g.qrow;
#pragma unroll
        for (int nt = 0; nt < 4; ++nt) {
            int col = g.n0 + g.warp_n + nt * 8 + 2 * g.qcol;
            float b0v = __ldg(&bias[col]);
            float b1v = __ldg(&bias[col + 1]);
            *(float2*)(C + (size_t)row * H_ + col) =
                make_float2(g.acc[mt * 4 + nt][0] + b0v, g.acc[mt * 4 + nt][1] + b1v);
            *(float2*)(C + (size_t)(row + 8) * H_ + col) =
                make_float2(g.acc[mt * 4 + nt][2] + b0v, g.acc[mt * 4 + nt][3] + b1v);
        }
    }
}

// ===========================================================================
// fp16 mma flash attention. CTA: 128 Q rows, 8 warps. KV chunk 64,
// 3-stage cp.async, ONE barrier per chunk, occ 2. pi-permuted operands,
// RSTH=80 conflict-free LDS.64 fragments.
// R14: exp(t) interleaved with PV(t) per 16-col kv block -> MUFU/tensor overlap.
// ===========================================================================
#define KVC 64
#define NCH (S_ / KVC)          // 32
#define RSTH 80                 // smem row stride in halves (64 data + 16 pad)
#define TILE_HALVES (64 * RSTH)               // 5120
#define STG_HALVES  (2 * TILE_HALVES)         // K + Vt, one stage = 10240
#define ATT_SMEM_BYTES (3 * STG_HALVES * 2)   // 61440

__global__ __launch_bounds__(256, 2)
void attn_mma_kernel(const __half* __restrict__ Qh, const __half* __restrict__ Kh,
                     const __half* __restrict__ Vth, const __half* __restrict__ FMh,
                     __half* __restrict__ Oh)
{
    extern __shared__ __half smh[];
    const uint32_t sb = smem_u32(smh);

    const int tid  = threadIdx.x;
    const int wid  = tid >> 5;
    const int lane = tid & 31;
    const int gr   = lane >> 2;    // 0..7
    const int qc   = lane & 3;     // 0..3
    const int q0   = blockIdx.x * 128;
    const int h    = blockIdx.y;
    const int b    = blockIdx.z;
    const int wrow = wid * 16;
    const float L2E = 1.44269504f;

    const size_t base   = (size_t)b * S_ * H_ + (size_t)h * HD_;       // Q/K halves
    const size_t vtbase = (size_t)(b * NH_ + h) * HD_ * S_;            // Vt halves

    uint32_t qf[4][4];
    {
        const __half* Qr0 = Qh + base + (size_t)(q0 + wrow + gr) * H_;
        const __half* Qr1 = Qh + base + (size_t)(q0 + wrow + gr + 8) * H_;
#pragma unroll
        for (int ks = 0; ks < 4; ++ks) {
            int c = ks * 16 + 4 * qc;
            uint2 lo = *(const uint2*)(Qr0 + c);
            uint2 hi = *(const uint2*)(Qr1 + c);
            qf[ks][0] = lo.x; qf[ks][1] = hi.x;
            qf[ks][2] = lo.y; qf[ks][3] = hi.y;
        }
    }

    float oacc[8][4];
#pragma unroll
    for (int i = 0; i < 8; ++i)
#pragma unroll
        for (int j = 0; j < 4; ++j) oacc[i][j] = 0.0f;
    float m_lo = -1e30f, m_hi = -1e30f, l_lo = 0.0f, l_hi = 0.0f;   // l lane-local

    const int prow = tid >> 3;          // 0..31
    const int pch  = tid & 7;           // 0..7

    auto issue_chunk = [&](int c) {
        const uint32_t kb = sb + (uint32_t)((c % 3) * STG_HALVES) * 2;
        const uint32_t vb = kb + (uint32_t)TILE_HALVES * 2;
        const int k0 = c * KVC;
#pragma unroll
        for (int it = 0; it < 2; ++it) {
            int r = prow + it * 32;     // 0..63
            cp_async16(kb + (uint32_t)(r * RSTH + pch * 8) * 2,
                       Kh + base + (size_t)(k0 + r) * H_ + pch * 8);
            cp_async16(vb + (uint32_t)(r * RSTH + pch * 8) * 2,
                       Vth + vtbase + (size_t)r * S_ + k0 + pch * 8);
        }
        cp_commit();
    };

    issue_chunk(0);
    issue_chunk(1);

    const size_t fmbase_lo = ((size_t)b * S_ + (q0 + wrow + gr)) * S_;
    const size_t fmbase_hi = fmbase_lo + (size_t)8 * S_;

    for (int c = 0; c < NCH; ++c) {
        cp_wait<1>();
        __syncthreads();
        if (c + 2 < NCH) issue_chunk(c + 2);
        else cp_commit();

        const __half* Ks = smh + (c % 3) * STG_HALVES;
        const __half* Vs = Ks + TILE_HALVES;
        const int k0 = c * KVC;

        // ---- S = Q K^T (uint2 LDS.64 fragment loads) ----
        float sv[8][4];
#pragma unroll
        for (int i = 0; i < 8; ++i)
#pragma unroll
            for (int j = 0; j < 4; ++j) sv[i][j] = 0.0f;

#pragma unroll
        for (int ks = 0; ks < 4; ++ks) {
            const int kk = ks * 16 + 4 * qc;
#pragma unroll
            for (int nt = 0; nt < 8; ++nt) {
                uint2 bb = *(const uint2*)(Ks + (nt * 8 + gr) * RSTH + kk);
                mma_f16(sv[nt][0], sv[nt][1], sv[nt][2], sv[nt][3],
                        qf[ks][0], qf[ks][1], qf[ks][2], qf[ks][3], bb.x, bb.y);
            }
        }

        // ---- fused mask (fp16, streaming) + row max ----
        float tmax_lo = -1e30f, tmax_hi = -1e30f;
#pragma unroll
        for (int nt = 0; nt < 8; ++nt) {
            int colo = k0 + nt * 8 + 2 * qc;
            uint32_t ul = __ldcs((const uint32_t*)(FMh + fmbase_lo + colo));
            uint32_t uh = __ldcs((const uint32_t*)(FMh + fmbase_hi + colo));
            float2 fl = __half22float2(*(const __half2*)&ul);
            float2 fh = __half22float2(*(const __half2*)&uh);
            float s0 = (fl.x < 0.0f) ? -1e30f : sv[nt][0] * fl.x;
            float s1 = (fl.y < 0.0f) ? -1e30f : sv[nt][1] * fl.y;
            float s2 = (fh.x < 0.0f) ? -1e30f : sv[nt][2] * fh.x;
            float s3 = (fh.y < 0.0f) ? -1e30f : sv[nt][3] * fh.y;
            sv[nt][0] = s0; sv[nt][1] = s1; sv[nt][2] = s2; sv[nt][3] = s3;
            tmax_lo = fmaxf(tmax_lo, fmaxf(s0, s1));
            tmax_hi = fmaxf(tmax_hi, fmaxf(s2, s3));
        }
        tmax_lo = fmaxf(tmax_lo, __shfl_xor_sync(0xffffffffu, tmax_lo, 1));
        tmax_lo = fmaxf(tmax_lo, __shfl_xor_sync(0xffffffffu, tmax_lo, 2));
        tmax_hi = fmaxf(tmax_hi, __shfl_xor_sync(0xffffffffu, tmax_hi, 1));
        tmax_hi = fmaxf(tmax_hi, __shfl_xor_sync(0xffffffffu, tmax_hi, 2));

        float newm_lo = fmaxf(m_lo, tmax_lo);
        float newm_hi = fmaxf(m_hi, tmax_hi);
        float alpha_lo = __expf(m_lo - newm_lo);
        float alpha_hi = __expf(m_hi - newm_hi);
        m_lo = newm_lo; m_hi = newm_hi;

        // ---- rescale O (before interleaved exp/PV) ----
#pragma unroll
        for (int nt = 0; nt < 8; ++nt) {
            oacc[nt][0] *= alpha_lo; oacc[nt][1] *= alpha_lo;
            oacc[nt][2] *= alpha_hi; oacc[nt][3] *= alpha_hi;
        }
        l_lo *= alpha_lo;
        l_hi *= alpha_hi;

        // ---- interleaved: exp(block t) then PV(block t) — MUFU || tensor ----
        const float ml_lo = newm_lo * L2E;
        const float ml_hi = newm_hi * L2E;
        float rs_lo = 0.0f, rs_hi = 0.0f;
#pragma unroll
        for (int t = 0; t < 4; ++t) {
            // exp for kv cols [16t, 16t+16): nt = 2t, 2t+1
            uint32_t a0, a1, a2, a3;
            {
                const int n0i = 2 * t;
                float t0 = fmaf(sv[n0i][0], L2E, -ml_lo);
                float t1 = fmaf(sv[n0i][1], L2E, -ml_lo);
                float t2 = fmaf(sv[n0i][2], L2E, -ml_hi);
                float t3 = fmaf(sv[n0i][3], L2E, -ml_hi);
                a0 = ex2_h2(packh2(t0, t1));
                a1 = ex2_h2(packh2(t2, t3));
                float u0 = fmaf(sv[n0i + 1][0], L2E, -ml_lo);
                float u1 = fmaf(sv[n0i + 1][1], L2E, -ml_lo);
                float u2 = fmaf(sv[n0i + 1][2], L2E, -ml_hi);
                float u3 = fmaf(sv[n0i + 1][3], L2E, -ml_hi);
                a2 = ex2_h2(packh2(u0, u1));
                a3 = ex2_h2(packh2(u2, u3));
                float2 f0 = __half22float2(*(const __half2*)&a0);
                float2 f1 = __half22float2(*(const __half2*)&a1);
                float2 f2 = __half22float2(*(const __half2*)&a2);
                float2 f3 = __half22float2(*(const __half2*)&a3);
                rs_lo += f0.x + f0.y + f2.x + f2.y;
                rs_hi += f1.x + f1.y + f3.x + f3.y;
            }
            // PV for this block: A-frag = (a0,a1,a2,a3)
            const int kk = t * 16 + 4 * qc;
#pragma unroll
            for (int nt = 0; nt < 8; ++nt) {
                uint2 bb = *(const uint2*)(Vs + (nt * 8 + gr) * RSTH + kk);
                mma_f16(oacc[nt][0], oacc[nt][1], oacc[nt][2], oacc[nt][3],
                        a0, a1, a2, a3, bb.x, bb.y);
            }
        }
        l_lo += rs_lo;
        l_hi += rs_hi;
    }

    // ---- final l reduction + epilogue: natural-order fp16 AO ----
    l_lo += __shfl_xor_sync(0xffffffffu, l_lo, 1);
    l_lo += __shfl_xor_sync(0xffffffffu, l_lo, 2);
    l_hi += __shfl_xor_sync(0xffffffffu, l_hi, 1);
    l_hi += __shfl_xor_sync(0xffffffffu, l_hi, 2);
    float inv_lo = 1.0f / l_lo;
    float inv_hi = 1.0f / l_hi;
    __half* Or0 = Oh + base + (size_t)(q0 + wrow + gr) * H_;
    __half* Or1 = Oh + base + (size_t)(q0 + wrow + gr + 8) * H_;
#pragma unroll
    for (int nt = 0; nt < 8; ++nt) {
        int col = nt * 8 + 2 * qc;
        *(uint32_t*)(Or0 + col) = packh2(oacc[nt][0] * inv_lo, oacc[nt][1] * inv_lo);
        *(uint32_t*)(Or1 + col) = packh2(oacc[nt][2] * inv_hi, oacc[nt][3] * inv_hi);
    }
}

// ---------------------------------------------------------------------------
extern "C" void kernel_launch(void* const* d_in, const int* in_sizes, int n_in,
                              void* d_out, int out_size)
{
    const float* query = (const float*)d_in[0];
    const float* key   = (const float*)d_in[1];
    const float* value = (const float*)d_in[2];
    const int*   mask  = (const int*)d_in[3];
    const float* smask = (const float*)d_in[4];
    const float* Wq = (const float*)d_in[5];
    const float* bq = (const float*)d_in[6];
    const float* Wk = (const float*)d_in[7];
    const float* bk = (const float*)d_in[8];
    const float* Wv = (const float*)d_in[9];
    const float* bv = (const float*)d_in[10];
    const float* Wo = (const float*)d_in[11];
    const float* bo = (const float*)d_in[12];
    float* out = (float*)d_out;

    __half *ginh, *gwh, *gqh, *gkh, *gvt, *gaoh, *gfmh;
    cudaGetSymbolAddress((void**)&ginh, g_INh);
    cudaGetSymbolAddress((void**)&gwh,  g_Wh);
    cudaGetSymbolAddress((void**)&gqh,  g_Qh);
    cudaGetSymbolAddress((void**)&gkh,  g_Kh);
    cudaGetSymbolAddress((void**)&gvt,  g_Vt);
    cudaGetSymbolAddress((void**)&gaoh, g_AOh);
    cudaGetSymbolAddress((void**)&gfmh, g_FMh);

    cudaFuncSetAttribute(qkv_gemm_kernel,
                         cudaFuncAttributeMaxDynamicSharedMemorySize, G_SMEM_BYTES);
    cudaFuncSetAttribute(out_gemm_kernel,
                         cudaFuncAttributeMaxDynamicSharedMemorySize, G_SMEM_BYTES);
    cudaFuncSetAttribute(attn_mma_kernel,
                         cudaFuncAttributeMaxDynamicSharedMemorySize, ATT_SMEM_BYTES);

    dim3 cgrid(M_ * H_ / 4 / 256, 7);      // (4096, 7)
    cvt_kernel<<<cgrid, 256>>>(query, key, value, Wq, Wk, Wv, Wo, ginh, gwh);

    fuse_mask_kernel<<<(B_ * S_ * S_ / 4) / 256, 256>>>(mask, smask, gfmh);

    dim3 gblk(256);
    dim3 qkvgrid(H_ / 128, M_ / 128, 3);   // (8, 32, 3)
    qkv_gemm_kernel<<<qkvgrid, gblk, G_SMEM_BYTES>>>(
        ginh, gwh, bq, bk, bv, gqh, gkh, gvt);

    dim3 agrid(S_ / 128, NH_, B_);         // (16, 16, 2)
    attn_mma_kernel<<<agrid, 256, ATT_SMEM_BYTES>>>(gqh, gkh, gvt, gfmh, gaoh);

    dim3 ogrid(H_ / 128, M_ / 128);        // (8, 32)
    out_gemm_kernel<<<ogrid, gblk, G_SMEM_BYTES>>>(gaoh, gwh, bo, out);
}

// round 15
// speedup vs baseline: 1.0223x; 1.0223x over previous
#include <cuda_runtime.h>
#include <cuda_fp16.h>
#include <cstdint>
#include <cstddef>

#define B_  2
#define S_  2048
#define H_  1024
#define NH_ 16
#define HD_ 64
#define M_  (B_ * S_)   // 4096 rows

// Scratch (allocation-free rule: __device__ globals)
// Qh/Kh: hd-dim pi-permuted within 16-blocks (old pair (2q,2q+1)->pos 4q,
// old pair (2q+8,2q+9)->pos 4q+2). Vt: s-dim pi-permuted the same way.
__device__ __align__(16) __half g_INh[(size_t)3 * M_ * H_];            // q,k,v inputs fp16
__device__ __align__(16) __half g_Wh[(size_t)4 * H_ * H_];             // Wq,Wk,Wv,Wo fp16
__device__ __align__(16) __half g_Qh[(size_t)M_ * H_];                 // [b][s][h] fp16 (hd pi)
__device__ __align__(16) __half g_Kh[(size_t)M_ * H_];                 // [b][s][h] fp16 (hd pi)
__device__ __align__(16) __half g_Vt[(size_t)B_ * NH_ * HD_ * S_];     // [b][h][hd][s] fp16 (s pi)
__device__ __align__(16) __half g_AOh[(size_t)M_ * H_];                // attn out fp16 (natural)
__device__ __align__(16) __half g_FMh[(size_t)B_ * S_ * S_];           // -1 or sm*0.125 (fp16)

// ---------------------------------------------------------------------------
__device__ __forceinline__ uint32_t packh2(float lo, float hi) {
    uint32_t d;
    asm("cvt.rn.f16x2.f32 %0, %1, %2;" : "=r"(d) : "f"(hi), "f"(lo));
    return d;
}
__device__ __forceinline__ uint32_t ex2_h2(uint32_t t) {
    uint32_t d;
    asm("ex2.approx.f16x2 %0, %1;" : "=r"(d) : "r"(t));
    return d;
}

__device__ __forceinline__ void mma_f16(float& d0, float& d1, float& d2, float& d3,
                                        uint32_t a0, uint32_t a1, uint32_t a2, uint32_t a3,
                                        uint32_t b0, uint32_t b1) {
    asm volatile(
        "mma.sync.aligned.m16n8k16.row.col.f32.f16.f16.f32 "
        "{%0,%1,%2,%3}, {%4,%5,%6,%7}, {%8,%9}, {%0,%1,%2,%3};"
        : "+f"(d0), "+f"(d1), "+f"(d2), "+f"(d3)
        : "r"(a0), "r"(a1), "r"(a2), "r"(a3), "r"(b0), "r"(b1));
}

__device__ __forceinline__ uint32_t smem_u32(const void* p) {
    uint32_t a;
    asm("{ .reg .u64 t; cvta.to.shared.u64 t, %1; cvt.u32.u64 %0, t; }"
        : "=r"(a) : "l"(p));
    return a;
}
__device__ __forceinline__ void cp_async16(uint32_t dst, const void* src) {
    asm volatile("cp.async.cg.shared.global [%0], [%1], 16;"
                 :: "r"(dst), "l"(src) : "memory");
}
__device__ __forceinline__ void cp_commit() {
    asm volatile("cp.async.commit_group;" ::: "memory");
}
template <int N>
__device__ __forceinline__ void cp_wait() {
    asm volatile("cp.async.wait_group %0;" :: "n"(N) : "memory");
}

// ===========================================================================
// Merged prologue: inputs->fp16, weights->fp16, fused mask->fp16.
// One 1D grid over 16-byte work items:
//   [0, 3*2^20)        : q/k/v cvt   (plane = i>>20, idx = i & (2^20-1))
//   [3*2^20, 4*2^20)   : weights cvt (w = j>>18, idx = j & (2^18-1))
//   [4*2^20, 6*2^20)   : mask fuse
// ===========================================================================
#define PRO_IN_END   (3u << 20)
#define PRO_W_END    (4u << 20)
#define PRO_TOTAL    (6u << 20)
#define PRO_CTAS     (PRO_TOTAL / 256)   // 24576

__global__ __launch_bounds__(256)
void prologue_kernel(const float* __restrict__ q, const float* __restrict__ k,
                     const float* __restrict__ v,
                     const float* __restrict__ wq, const float* __restrict__ wk,
                     const float* __restrict__ wv, const float* __restrict__ wo,
                     const int* __restrict__ mask, const float* __restrict__ sm,
                     __half* __restrict__ inh, __half* __restrict__ wh,
                     __half* __restrict__ fm)
{
    const uint32_t i = blockIdx.x * 256 + threadIdx.x;
    if (i < PRO_IN_END) {
        const uint32_t plane = i >> 20;
        const uint32_t idx   = i & ((1u << 20) - 1);
        const float* src = (plane == 0) ? q : (plane == 1) ? k : v;
        float4 f = ((const float4*)src)[idx];
        uint2 o;
        o.x = packh2(f.x, f.y);
        o.y = packh2(f.z, f.w);
        ((uint2*)inh)[((size_t)plane << 20) + idx] = o;
    } else if (i < PRO_W_END) {
        const uint32_t j   = i - PRO_IN_END;
        const uint32_t w   = j >> 18;
        const uint32_t idx = j & ((1u << 18) - 1);
        const float* src = (w == 0) ? wq : (w == 1) ? wk : (w == 2) ? wv : wo;
        float4 f = ((const float4*)src)[idx];
        uint2 o;
        o.x = packh2(f.x, f.y);
        o.y = packh2(f.z, f.w);
        ((uint2*)wh)[((size_t)w << 18) + idx] = o;
    } else {
        const uint32_t idx = i - PRO_W_END;
        int4   m = ((const int4*)mask)[idx];
        float4 s = ((const float4*)sm)[idx];
        float o0 = (m.x == 0) ? -1.0f : s.x * 0.125f;
        float o1 = (m.y == 0) ? -1.0f : s.y * 0.125f;
        float o2 = (m.z == 0) ? -1.0f : s.z * 0.125f;
        float o3 = (m.w == 0) ? -1.0f : s.w * 0.125f;
        uint2 o;
        o.x = packh2(o0, o1);
        o.y = packh2(o2, o3);
        ((uint2*)fm)[idx] = o;
    }
}

// ===========================================================================
// fp16 GEMM core (R10-proven, unchanged): acc = X @ W^T. CTA 128x128,
// warp 64x32, K chunk 32, 3-stage cp.async, ONE barrier per chunk, RS=40.
// ===========================================================================
#define RS 40
#define G_STAGE_HALVES (2 * 128 * RS)              // A + B, one stage = 10240
#define G_SMEM_BYTES   (3 * G_STAGE_HALVES * 2)    // 61440
#define G_NCHUNK (H_ / 32)                          // 32

struct GemmCtx {
    int warp_m, warp_n, qrow, qcol, m0, n0;
    float acc[16][4];
};

__device__ __forceinline__ void gemm_compute(
    GemmCtx& g, const __half* __restrict__ X, const __half* __restrict__ W)
{
    extern __shared__ __half gsh[];
    const uint32_t sb = smem_u32(gsh);

    const int tid  = threadIdx.x;
    const int wid  = tid >> 5;
    const int lane = tid & 31;
    g.m0 = blockIdx.y * 128;
    g.n0 = blockIdx.x * 128;
    g.warp_m = (wid & 1) * 64;
    g.warp_n = (wid >> 1) * 32;
    g.qrow = lane >> 2;
    g.qcol = lane & 3;

    const int r0 = tid >> 1;            // 0..127
    const int h0 = (tid & 1) * 16;      // half-offset base in row

    const __half* Xa = X + (size_t)(g.m0 + r0) * H_ + h0;
    const __half* Wb = W + (size_t)(g.n0 + r0) * H_ + h0;
    const uint32_t da = sb + (uint32_t)(r0 * RS + h0) * 2;
    const uint32_t db = da + (uint32_t)(128 * RS) * 2;

    auto issue = [&](int c) {
        const uint32_t so = (uint32_t)((c % 3) * G_STAGE_HALVES) * 2;
        const int k0 = c * 32;
        cp_async16(da + so,      Xa + k0);
        cp_async16(da + so + 16, Xa + k0 + 8);
        cp_async16(db + so,      Wb + k0);
        cp_async16(db + so + 16, Wb + k0 + 8);
        cp_commit();
    };

#pragma unroll
    for (int i = 0; i < 16; ++i)
#pragma unroll
        for (int j = 0; j < 4; ++j) g.acc[i][j] = 0.0f;

    issue(0);
    issue(1);

    for (int c = 0; c < G_NCHUNK; ++c) {
        cp_wait<1>();
        __syncthreads();
        if (c + 2 < G_NCHUNK) issue(c + 2);
        else cp_commit();

        const __half* As = gsh + (c % 3) * G_STAGE_HALVES;
        const __half* Bs = As + 128 * RS;

#pragma unroll
        for (int ks = 0; ks < 2; ++ks) {
            const int kk = ks * 16 + 2 * g.qcol;
            uint32_t af[4][4];
            uint32_t bf[4][2];
#pragma unroll
            for (int mt = 0; mt < 4; ++mt) {
                const __half* ap = As + (g.warp_m + mt * 16 + g.qrow) * RS + kk;
                af[mt][0] = *(const uint32_t*)ap;
                af[mt][1] = *(const uint32_t*)(ap + 8 * RS);
                af[mt][2] = *(const uint32_t*)(ap + 8);
                af[mt][3] = *(const uint32_t*)(ap + 8 * RS + 8);
            }
#pragma unroll
            for (int nt = 0; nt < 4; ++nt) {
                const __half* bp = Bs + (g.warp_n + nt * 8 + g.qrow) * RS + kk;
                bf[nt][0] = *(const uint32_t*)bp;
                bf[nt][1] = *(const uint32_t*)(bp + 8);
            }
#pragma unroll
            for (int mt = 0; mt < 4; ++mt)
#pragma unroll
                for (int nt = 0; nt < 4; ++nt)
                    mma_f16(g.acc[mt * 4 + nt][0], g.acc[mt * 4 + nt][1],
                            g.acc[mt * 4 + nt][2], g.acc[mt * 4 + nt][3],
                            af[mt][0], af[mt][1], af[mt][2], af[mt][3],
                            bf[nt][0], bf[nt][1]);
        }
    }
}

// Fused Q/K/V projections. z=0/1 -> fp16 [b][s][h] pi-store (hd);
// z=2 -> fp16 V^T store with pi-permuted s.
__global__ __launch_bounds__(256, 2)
void qkv_gemm_kernel(const __half* __restrict__ inh, const __half* __restrict__ wh,
                     const float* __restrict__ bq, const float* __restrict__ bk,
                     const float* __restrict__ bv,
                     __half* __restrict__ Cq, __half* __restrict__ Ck,
                     __half* __restrict__ Cvt)
{
    const int z = blockIdx.z;
    const __half* X = inh + (size_t)z * M_ * H_;
    const __half* W = wh + (size_t)z * H_ * H_;
    const float* bias = (z == 0) ? bq : (z == 1) ? bk : bv;

    GemmCtx g;
    gemm_compute(g, X, W);

    if (z < 2) {
        __half* C = (z == 0) ? Cq : Ck;
#pragma unroll
        for (int mt = 0; mt < 4; ++mt) {
            int row = g.m0 + g.warp_m + mt * 16 + g.qrow;
#pragma unroll
            for (int nt = 0; nt < 4; ++nt) {
                int col = g.n0 + g.warp_n + nt * 8 + 2 * g.qcol;   // natural col
                int ncol = (col & ~15) + 4 * g.qcol + ((nt & 1) << 1);
                float b0v = __ldg(&bias[col]);
                float b1v = __ldg(&bias[col + 1]);
                uint32_t h0v = packh2(g.acc[mt * 4 + nt][0] + b0v,
                                      g.acc[mt * 4 + nt][1] + b1v);
                uint32_t h1v = packh2(g.acc[mt * 4 + nt][2] + b0v,
                                      g.acc[mt * 4 + nt][3] + b1v);
                *(uint32_t*)(C + (size_t)row * H_ + ncol)       = h0v;
                *(uint32_t*)(C + (size_t)(row + 8) * H_ + ncol) = h1v;
            }
        }
    } else {
        // V transposed: [b][h][hd][s], s pi-permuted within 16-blocks
#pragma unroll
        for (int mt = 0; mt < 4; ++mt) {
            int srow = g.m0 + g.warp_m + mt * 16 + g.qrow;
            int bb = srow >> 11, s = srow & 2047;
            int j = s & 15;                       // 0..7 here (qrow 0..7)
            int pos0 = (s & ~15) + 4 * (j >> 1) + (j & 1);   // old row j
#pragma unroll
            for (int nt = 0; nt < 4; ++nt) {
                int col = g.n0 + g.warp_n + nt * 8 + 2 * g.qcol;
                float b0v = __ldg(&bias[col]);
                float b1v = __ldg(&bias[col + 1]);
                int hh = col >> 6, hd = col & 63;
                __half* p = Cvt + ((size_t)(bb * NH_ + hh) * HD_ + hd) * S_;
                p[pos0]          = __float2half_rn(g.acc[mt * 4 + nt][0] + b0v);
                p[S_ + pos0]     = __float2half_rn(g.acc[mt * 4 + nt][1] + b1v);
                p[pos0 + 2]      = __float2half_rn(g.acc[mt * 4 + nt][2] + b0v);
                p[S_ + pos0 + 2] = __float2half_rn(g.acc[mt * 4 + nt][3] + b1v);
            }
        }
    }
}

__global__ __launch_bounds__(256, 2)
void out_gemm_kernel(const __half* __restrict__ X, const __half* __restrict__ wh,
                     const float* __restrict__ bias, float* __restrict__ C)
{
    GemmCtx g;
    gemm_compute(g, X, wh + (size_t)3 * H_ * H_);
#pragma unroll
    for (int mt = 0; mt < 4; ++mt) {
        int row = g.m0 + g.warp_m + mt * 16 + g.qrow;
#pragma unroll
        for (int nt = 0; nt < 4; ++nt) {
            int col = g.n0 + g.warp_n + nt * 8 + 2 * g.qcol;
            float b0v = __ldg(&bias[col]);
            float b1v = __ldg(&bias[col + 1]);
            *(float2*)(C + (size_t)row * H_ + col) =
                make_float2(g.acc[mt * 4 + nt][0] + b0v, g.acc[mt * 4 + nt][1] + b1v);
            *(float2*)(C + (size_t)(row + 8) * H_ + col) =
                make_float2(g.acc[mt * 4 + nt][2] + b0v, g.acc[mt * 4 + nt][3] + b1v);
        }
    }
}

// ===========================================================================
// fp16 mma flash attention (R13/R14-proven). CTA: 128 Q rows, 8 warps.
// KV chunk 64, 3-stage cp.async, ONE barrier per chunk, occ 2.
// pi-permuted operands, RSTH=80 conflict-free LDS.64 fragments.
// exp(t) interleaved with PV(t) per 16-col kv block.
// ===========================================================================
#define KVC 64
#define NCH (S_ / KVC)          // 32
#define RSTH 80                 // smem row stride in halves (64 data + 16 pad)
#define TILE_HALVES (64 * RSTH)               // 5120
#define STG_HALVES  (2 * TILE_HALVES)         // K + Vt, one stage = 10240
#define ATT_SMEM_BYTES (3 * STG_HALVES * 2)   // 61440

__global__ __launch_bounds__(256, 2)
void attn_mma_kernel(const __half* __restrict__ Qh, const __half* __restrict__ Kh,
                     const __half* __restrict__ Vth, const __half* __restrict__ FMh,
                     __half* __restrict__ Oh)
{
    extern __shared__ __half smh[];
    const uint32_t sb = smem_u32(smh);

    const int tid  = threadIdx.x;
    const int wid  = tid >> 5;
    const int lane = tid & 31;
    const int gr   = lane >> 2;    // 0..7
    const int qc   = lane & 3;     // 0..3
    const int q0   = blockIdx.x * 128;
    const int h    = blockIdx.y;
    const int b    = blockIdx.z;
    const int wrow = wid * 16;
    const float L2E = 1.44269504f;

    const size_t base   = (size_t)b * S_ * H_ + (size_t)h * HD_;       // Q/K halves
    const size_t vtbase = (size_t)(b * NH_ + h) * HD_ * S_;            // Vt halves

    uint32_t qf[4][4];
    {
        const __half* Qr0 = Qh + base + (size_t)(q0 + wrow + gr) * H_;
        const __half* Qr1 = Qh + base + (size_t)(q0 + wrow + gr + 8) * H_;
#pragma unroll
        for (int ks = 0; ks < 4; ++ks) {
            int c = ks * 16 + 4 * qc;
            uint2 lo = *(const uint2*)(Qr0 + c);
            uint2 hi = *(const uint2*)(Qr1 + c);
            qf[ks][0] = lo.x; qf[ks][1] = hi.x;
            qf[ks][2] = lo.y; qf[ks][3] = hi.y;
        }
    }

    float oacc[8][4];
#pragma unroll
    for (int i = 0; i < 8; ++i)
#pragma unroll
        for (int j = 0; j < 4; ++j) oacc[i][j] = 0.0f;
    float m_lo = -1e30f, m_hi = -1e30f, l_lo = 0.0f, l_hi = 0.0f;   // l lane-local

    const int prow = tid >> 3;          // 0..31
    const int pch  = tid & 7;           // 0..7

    auto issue_chunk = [&](int c) {
        const uint32_t kb = sb + (uint32_t)((c % 3) * STG_HALVES) * 2;
        const uint32_t vb = kb + (uint32_t)TILE_HALVES * 2;
        const int k0 = c * KVC;
#pragma unroll
        for (int it = 0; it < 2; ++it) {
            int r = prow + it * 32;     // 0..63
            cp_async16(kb + (uint32_t)(r * RSTH + pch * 8) * 2,
                       Kh + base + (size_t)(k0 + r) * H_ + pch * 8);
            cp_async16(vb + (uint32_t)(r * RSTH + pch * 8) * 2,
                       Vth + vtbase + (size_t)r * S_ + k0 + pch * 8);
        }
        cp_commit();
    };

    issue_chunk(0);
    issue_chunk(1);

    const size_t fmbase_lo = ((size_t)b * S_ + (q0 + wrow + gr)) * S_;
    const size_t fmbase_hi = fmbase_lo + (size_t)8 * S_;

    for (int c = 0; c < NCH; ++c) {
        cp_wait<1>();
        __syncthreads();
        if (c + 2 < NCH) issue_chunk(c + 2);
        else cp_commit();

        const __half* Ks = smh + (c % 3) * STG_HALVES;
        const __half* Vs = Ks + TILE_HALVES;
        const int k0 = c * KVC;

        // ---- S = Q K^T (uint2 LDS.64 fragment loads) ----
        float sv[8][4];
#pragma unroll
        for (int i = 0; i < 8; ++i)
#pragma unroll
            for (int j = 0; j < 4; ++j) sv[i][j] = 0.0f;

#pragma unroll
        for (int ks = 0; ks < 4; ++ks) {
            const int kk = ks * 16 + 4 * qc;
#pragma unroll
            for (int nt = 0; nt < 8; ++nt) {
                uint2 bb = *(const uint2*)(Ks + (nt * 8 + gr) * RSTH + kk);
                mma_f16(sv[nt][0], sv[nt][1], sv[nt][2], sv[nt][3],
                        qf[ks][0], qf[ks][1], qf[ks][2], qf[ks][3], bb.x, bb.y);
            }
        }

        // ---- fused mask (fp16, streaming) + row max ----
        float tmax_lo = -1e30f, tmax_hi = -1e30f;
#pragma unroll
        for (int nt = 0; nt < 8; ++nt) {
            int colo = k0 + nt * 8 + 2 * qc;
            uint32_t ul = __ldcs((const uint32_t*)(FMh + fmbase_lo + colo));
            uint32_t uh = __ldcs((const uint32_t*)(FMh + fmbase_hi + colo));
            float2 fl = __half22float2(*(const __half2*)&ul);
            float2 fh = __half22float2(*(const __half2*)&uh);
            float s0 = (fl.x < 0.0f) ? -1e30f : sv[nt][0] * fl.x;
            float s1 = (fl.y < 0.0f) ? -1e30f : sv[nt][1] * fl.y;
            float s2 = (fh.x < 0.0f) ? -1e30f : sv[nt][2] * fh.x;
            float s3 = (fh.y < 0.0f) ? -1e30f : sv[nt][3] * fh.y;
            sv[nt][0] = s0; sv[nt][1] = s1; sv[nt][2] = s2; sv[nt][3] = s3;
            tmax_lo = fmaxf(tmax_lo, fmaxf(s0, s1));
            tmax_hi = fmaxf(tmax_hi, fmaxf(s2, s3));
        }
        tmax_lo = fmaxf(tmax_lo, __shfl_xor_sync(0xffffffffu, tmax_lo, 1));
        tmax_lo = fmaxf(tmax_lo, __shfl_xor_sync(0xffffffffu, tmax_lo, 2));
        tmax_hi = fmaxf(tmax_hi, __shfl_xor_sync(0xffffffffu, tmax_hi, 1));
        tmax_hi = fmaxf(tmax_hi, __shfl_xor_sync(0xffffffffu, tmax_hi, 2));

        float newm_lo = fmaxf(m_lo, tmax_lo);
        float newm_hi = fmaxf(m_hi, tmax_hi);
        float alpha_lo = __expf(m_lo - newm_lo);
        float alpha_hi = __expf(m_hi - newm_hi);
        m_lo = newm_lo; m_hi = newm_hi;

        // ---- rescale O ----
#pragma unroll
        for (int nt = 0; nt < 8; ++nt) {
            oacc[nt][0] *= alpha_lo; oacc[nt][1] *= alpha_lo;
            oacc[nt][2] *= alpha_hi; oacc[nt][3] *= alpha_hi;
        }
        l_lo *= alpha_lo;
        l_hi *= alpha_hi;

        // ---- interleaved: exp(block t) then PV(block t) ----
        const float ml_lo = newm_lo * L2E;
        const float ml_hi = newm_hi * L2E;
        float rs_lo = 0.0f, rs_hi = 0.0f;
#pragma unroll
        for (int t = 0; t < 4; ++t) {
            uint32_t a0, a1, a2, a3;
            {
                const int n0i = 2 * t;
                float t0 = fmaf(sv[n0i][0], L2E, -ml_lo);
                float t1 = fmaf(sv[n0i][1], L2E, -ml_lo);
                float t2 = fmaf(sv[n0i][2], L2E, -ml_hi);
                float t3 = fmaf(sv[n0i][3], L2E, -ml_hi);
                a0 = ex2_h2(packh2(t0, t1));
                a1 = ex2_h2(packh2(t2, t3));
                float u0 = fmaf(sv[n0i + 1][0], L2E, -ml_lo);
                float u1 = fmaf(sv[n0i + 1][1], L2E, -ml_lo);
                float u2 = fmaf(sv[n0i + 1][2], L2E, -ml_hi);
                float u3 = fmaf(sv[n0i + 1][3], L2E, -ml_hi);
                a2 = ex2_h2(packh2(u0, u1));
                a3 = ex2_h2(packh2(u2, u3));
                float2 f0 = __half22float2(*(const __half2*)&a0);
                float2 f1 = __half22float2(*(const __half2*)&a1);
                float2 f2 = __half22float2(*(const __half2*)&a2);
                float2 f3 = __half22float2(*(const __half2*)&a3);
                rs_lo += f0.x + f0.y + f2.x + f2.y;
                rs_hi += f1.x + f1.y + f3.x + f3.y;
            }
            const int kk = t * 16 + 4 * qc;
#pragma unroll
            for (int nt = 0; nt < 8; ++nt) {
                uint2 bb = *(const uint2*)(Vs + (nt * 8 + gr) * RSTH + kk);
                mma_f16(oacc[nt][0], oacc[nt][1], oacc[nt][2], oacc[nt][3],
                        a0, a1, a2, a3, bb.x, bb.y);
            }
        }
        l_lo += rs_lo;
        l_hi += rs_hi;
    }

    // ---- final l reduction + epilogue: natural-order fp16 AO ----
    l_lo += __shfl_xor_sync(0xffffffffu, l_lo, 1);
    l_lo += __shfl_xor_sync(0xffffffffu, l_lo, 2);
    l_hi += __shfl_xor_sync(0xffffffffu, l_hi, 1);
    l_hi += __shfl_xor_sync(0xffffffffu, l_hi, 2);
    float inv_lo = 1.0f / l_lo;
    float inv_hi = 1.0f / l_hi;
    __half* Or0 = Oh + base + (size_t)(q0 + wrow + gr) * H_;
    __half* Or1 = Oh + base + (size_t)(q0 + wrow + gr + 8) * H_;
#pragma unroll
    for (int nt = 0; nt < 8; ++nt) {
        int col = nt * 8 + 2 * qc;
        *(uint32_t*)(Or0 + col) = packh2(oacc[nt][0] * inv_lo, oacc[nt][1] * inv_lo);
        *(uint32_t*)(Or1 + col) = packh2(oacc[nt][2] * inv_hi, oacc[nt][3] * inv_hi);
    }
}

// ---------------------------------------------------------------------------
extern "C" void kernel_launch(void* const* d_in, const int* in_sizes, int n_in,
                              void* d_out, int out_size)
{
    const float* query = (const float*)d_in[0];
    const float* key   = (const float*)d_in[1];
    const float* value = (const float*)d_in[2];
    const int*   mask  = (const int*)d_in[3];
    const float* smask = (const float*)d_in[4];
    const float* Wq = (const float*)d_in[5];
    const float* bq = (const float*)d_in[6];
    const float* Wk = (const float*)d_in[7];
    const float* bk = (const float*)d_in[8];
    const float* Wv = (const float*)d_in[9];
    const float* bv = (const float*)d_in[10];
    const float* Wo = (const float*)d_in[11];
    const float* bo = (const float*)d_in[12];
    float* out = (float*)d_out;

    __half *ginh, *gwh, *gqh, *gkh, *gvt, *gaoh, *gfmh;
    cudaGetSymbolAddress((void**)&ginh, g_INh);
    cudaGetSymbolAddress((void**)&gwh,  g_Wh);
    cudaGetSymbolAddress((void**)&gqh,  g_Qh);
    cudaGetSymbolAddress((void**)&gkh,  g_Kh);
    cudaGetSymbolAddress((void**)&gvt,  g_Vt);
    cudaGetSymbolAddress((void**)&gaoh, g_AOh);
    cudaGetSymbolAddress((void**)&gfmh, g_FMh);

    cudaFuncSetAttribute(qkv_gemm_kernel,
                         cudaFuncAttributeMaxDynamicSharedMemorySize, G_SMEM_BYTES);
    cudaFuncSetAttribute(out_gemm_kernel,
                         cudaFuncAttributeMaxDynamicSharedMemorySize, G_SMEM_BYTES);
    cudaFuncSetAttribute(attn_mma_kernel,
                         cudaFuncAttributeMaxDynamicSharedMemorySize, ATT_SMEM_BYTES);

    // Merged prologue: cvt(q,k,v,W*) + mask fusion, one launch
    prologue_kernel<<<PRO_CTAS, 256>>>(query, key, value, Wq, Wk, Wv, Wo,
                                       mask, smask, ginh, gwh, gfmh);

    dim3 gblk(256);
    dim3 qkvgrid(H_ / 128, M_ / 128, 3);   // (8, 32, 3)
    qkv_gemm_kernel<<<qkvgrid, gblk, G_SMEM_BYTES>>>(
        ginh, gwh, bq, bk, bv, gqh, gkh, gvt);

    dim3 agrid(S_ / 128, NH_, B_);         // (16, 16, 2)
    attn_mma_kernel<<<agrid, 256, ATT_SMEM_BYTES>>>(gqh, gkh, gvt, gfmh, gaoh);

    dim3 ogrid(H_ / 128, M_ / 128);        // (8, 32)
    out_gemm_kernel<<<ogrid, gblk, G_SMEM_BYTES>>>(gaoh, gwh, bo, out);
}

// round 16
// speedup vs baseline: 1.0561x; 1.0331x over previous
#include <cuda_runtime.h>
#include <cuda_fp16.h>
#include <cstdint>
#include <cstddef>

#define B_  2
#define S_  2048
#define H_  1024
#define NH_ 16
#define HD_ 64
#define M_  (B_ * S_)   // 4096 rows

// Scratch (allocation-free rule: __device__ globals)
// Qh/Kh: hd-dim pi-permuted within 16-blocks (old pair (2q,2q+1)->pos 4q,
// old pair (2q+8,2q+9)->pos 4q+2). Vt: s-dim pi-permuted the same way.
__device__ __align__(16) __half g_INh[(size_t)3 * M_ * H_];            // q,k,v inputs fp16
__device__ __align__(16) __half g_Wh[(size_t)4 * H_ * H_];             // Wq,Wk,Wv,Wo fp16
__device__ __align__(16) __half g_Qh[(size_t)M_ * H_];                 // [b][s][h] fp16 (hd pi)
__device__ __align__(16) __half g_Kh[(size_t)M_ * H_];                 // [b][s][h] fp16 (hd pi)
__device__ __align__(16) __half g_Vt[(size_t)B_ * NH_ * HD_ * S_];     // [b][h][hd][s] fp16 (s pi)
__device__ __align__(16) __half g_AOh[(size_t)M_ * H_];                // attn out fp16 (natural)
__device__ __align__(16) __half g_FMh[(size_t)B_ * S_ * S_];           // -1 or sm*0.125 (fp16)

// ---------------------------------------------------------------------------
__device__ __forceinline__ uint32_t packh2(float lo, float hi) {
    uint32_t d;
    asm("cvt.rn.f16x2.f32 %0, %1, %2;" : "=r"(d) : "f"(hi), "f"(lo));
    return d;
}
__device__ __forceinline__ uint32_t ex2_h2(uint32_t t) {
    uint32_t d;
    asm("ex2.approx.f16x2 %0, %1;" : "=r"(d) : "r"(t));
    return d;
}

__device__ __forceinline__ void mma_f16(float& d0, float& d1, float& d2, float& d3,
                                        uint32_t a0, uint32_t a1, uint32_t a2, uint32_t a3,
                                        uint32_t b0, uint32_t b1) {
    asm volatile(
        "mma.sync.aligned.m16n8k16.row.col.f32.f16.f16.f32 "
        "{%0,%1,%2,%3}, {%4,%5,%6,%7}, {%8,%9}, {%0,%1,%2,%3};"
        : "+f"(d0), "+f"(d1), "+f"(d2), "+f"(d3)
        : "r"(a0), "r"(a1), "r"(a2), "r"(a3), "r"(b0), "r"(b1));
}

__device__ __forceinline__ uint32_t smem_u32(const void* p) {
    uint32_t a;
    asm("{ .reg .u64 t; cvta.to.shared.u64 t, %1; cvt.u32.u64 %0, t; }"
        : "=r"(a) : "l"(p));
    return a;
}
__device__ __forceinline__ void cp_async16(uint32_t dst, const void* src) {
    asm volatile("cp.async.cg.shared.global [%0], [%1], 16;"
                 :: "r"(dst), "l"(src) : "memory");
}
__device__ __forceinline__ void cp_commit() {
    asm volatile("cp.async.commit_group;" ::: "memory");
}
template <int N>
__device__ __forceinline__ void cp_wait() {
    asm volatile("cp.async.wait_group %0;" :: "n"(N) : "memory");
}

// ===========================================================================
// Prologue: inputs->fp16, weights->fp16 (mask fusion moved into qkv z=3).
// One 1D grid over 16-byte work items:
//   [0, 3*2^20)        : q/k/v cvt   (plane = i>>20, idx = i & (2^20-1))
//   [3*2^20, 4*2^20)   : weights cvt (w = j>>18, idx = j & (2^18-1))
// ===========================================================================
#define PRO_IN_END   (3u << 20)
#define PRO_TOTAL    (4u << 20)
#define PRO_CTAS     (PRO_TOTAL / 256)   // 16384

__global__ __launch_bounds__(256)
void prologue_kernel(const float* __restrict__ q, const float* __restrict__ k,
                     const float* __restrict__ v,
                     const float* __restrict__ wq, const float* __restrict__ wk,
                     const float* __restrict__ wv, const float* __restrict__ wo,
                     __half* __restrict__ inh, __half* __restrict__ wh)
{
    const uint32_t i = blockIdx.x * 256 + threadIdx.x;
    if (i < PRO_IN_END) {
        const uint32_t plane = i >> 20;
        const uint32_t idx   = i & ((1u << 20) - 1);
        const float* src = (plane == 0) ? q : (plane == 1) ? k : v;
        float4 f = ((const float4*)src)[idx];
        uint2 o;
        o.x = packh2(f.x, f.y);
        o.y = packh2(f.z, f.w);
        ((uint2*)inh)[((size_t)plane << 20) + idx] = o;
    } else {
        const uint32_t j   = i - PRO_IN_END;
        const uint32_t w   = j >> 18;
        const uint32_t idx = j & ((1u << 18) - 1);
        const float* src = (w == 0) ? wq : (w == 1) ? wk : (w == 2) ? wv : wo;
        float4 f = ((const float4*)src)[idx];
        uint2 o;
        o.x = packh2(f.x, f.y);
        o.y = packh2(f.z, f.w);
        ((uint2*)wh)[((size_t)w << 18) + idx] = o;
    }
}

// ===========================================================================
// fp16 GEMM core (R10-proven, unchanged): acc = X @ W^T. CTA 128x128,
// warp 64x32, K chunk 32, 3-stage cp.async, ONE barrier per chunk, RS=40.
// ===========================================================================
#define RS 40
#define G_STAGE_HALVES (2 * 128 * RS)              // A + B, one stage = 10240
#define G_SMEM_BYTES   (3 * G_STAGE_HALVES * 2)    // 61440
#define G_NCHUNK (H_ / 32)                          // 32

struct GemmCtx {
    int warp_m, warp_n, qrow, qcol, m0, n0;
    float acc[16][4];
};

__device__ __forceinline__ void gemm_compute(
    GemmCtx& g, const __half* __restrict__ X, const __half* __restrict__ W)
{
    extern __shared__ __half gsh[];
    const uint32_t sb = smem_u32(gsh);

    const int tid  = threadIdx.x;
    const int wid  = tid >> 5;
    const int lane = tid & 31;
    g.m0 = blockIdx.y * 128;
    g.n0 = blockIdx.x * 128;
    g.warp_m = (wid & 1) * 64;
    g.warp_n = (wid >> 1) * 32;
    g.qrow = lane >> 2;
    g.qcol = lane & 3;

    const int r0 = tid >> 1;            // 0..127
    const int h0 = (tid & 1) * 16;      // half-offset base in row

    const __half* Xa = X + (size_t)(g.m0 + r0) * H_ + h0;
    const __half* Wb = W + (size_t)(g.n0 + r0) * H_ + h0;
    const uint32_t da = sb + (uint32_t)(r0 * RS + h0) * 2;
    const uint32_t db = da + (uint32_t)(128 * RS) * 2;

    auto issue = [&](int c) {
        const uint32_t so = (uint32_t)((c % 3) * G_STAGE_HALVES) * 2;
        const int k0 = c * 32;
        cp_async16(da + so,      Xa + k0);
        cp_async16(da + so + 16, Xa + k0 + 8);
        cp_async16(db + so,      Wb + k0);
        cp_async16(db + so + 16, Wb + k0 + 8);
        cp_commit();
    };

#pragma unroll
    for (int i = 0; i < 16; ++i)
#pragma unroll
        for (int j = 0; j < 4; ++j) g.acc[i][j] = 0.0f;

    issue(0);
    issue(1);

    for (int c = 0; c < G_NCHUNK; ++c) {
        cp_wait<1>();
        __syncthreads();
        if (c + 2 < G_NCHUNK) issue(c + 2);
        else cp_commit();

        const __half* As = gsh + (c % 3) * G_STAGE_HALVES;
        const __half* Bs = As + 128 * RS;

#pragma unroll
        for (int ks = 0; ks < 2; ++ks) {
            const int kk = ks * 16 + 2 * g.qcol;
            uint32_t af[4][4];
            uint32_t bf[4][2];
#pragma unroll
            for (int mt = 0; mt < 4; ++mt) {
                const __half* ap = As + (g.warp_m + mt * 16 + g.qrow) * RS + kk;
                af[mt][0] = *(const uint32_t*)ap;
                af[mt][1] = *(const uint32_t*)(ap + 8 * RS);
                af[mt][2] = *(const uint32_t*)(ap + 8);
                af[mt][3] = *(const uint32_t*)(ap + 8 * RS + 8);
            }
#pragma unroll
            for (int nt = 0; nt < 4; ++nt) {
                const __half* bp = Bs + (g.warp_n + nt * 8 + g.qrow) * RS + kk;
                bf[nt][0] = *(const uint32_t*)bp;
                bf[nt][1] = *(const uint32_t*)(bp + 8);
            }
#pragma unroll
            for (int mt = 0; mt < 4; ++mt)
#pragma unroll
                for (int nt = 0; nt < 4; ++nt)
                    mma_f16(g.acc[mt * 4 + nt][0], g.acc[mt * 4 + nt][1],
                            g.acc[mt * 4 + nt][2], g.acc[mt * 4 + nt][3],
                            af[mt][0], af[mt][1], af[mt][2], af[mt][3],
                            bf[nt][0], bf[nt][1]);
        }
    }
}

// Fused Q/K/V projections + mask fusion.
// z=0/1 -> fp16 [b][s][h] pi-store (hd); z=2 -> fp16 V^T (s pi);
// z=3 -> mask fusion (memory-only CTAs, fill the GEMM wave tail).
__global__ __launch_bounds__(256, 2)
void qkv_gemm_kernel(const __half* __restrict__ inh, const __half* __restrict__ wh,
                     const float* __restrict__ bq, const float* __restrict__ bk,
                     const float* __restrict__ bv,
                     __half* __restrict__ Cq, __half* __restrict__ Ck,
                     __half* __restrict__ Cvt,
                     const int* __restrict__ mask, const float* __restrict__ sm,
                     __half* __restrict__ fm)
{
    const int z = blockIdx.z;
    if (z == 3) {
        // fm = (mask==0) ? -1 : sm * 0.125   (fp16), 2^21 16B items
        const int cta = blockIdx.y * gridDim.x + blockIdx.x;   // 0..255
        uint32_t i = cta * 256 + threadIdx.x;                  // stride 65536
        const int4*   m4 = (const int4*)mask;
        const float4* s4 = (const float4*)sm;
        uint2*        f4 = (uint2*)fm;
#pragma unroll
        for (int it = 0; it < 32; ++it, i += 65536) {
            int4   m = m4[i];
            float4 s = s4[i];
            float o0 = (m.x == 0) ? -1.0f : s.x * 0.125f;
            float o1 = (m.y == 0) ? -1.0f : s.y * 0.125f;
            float o2 = (m.z == 0) ? -1.0f : s.z * 0.125f;
            float o3 = (m.w == 0) ? -1.0f : s.w * 0.125f;
            uint2 o;
            o.x = packh2(o0, o1);
            o.y = packh2(o2, o3);
            f4[i] = o;
        }
        return;
    }

    const __half* X = inh + (size_t)z * M_ * H_;
    const __half* W = wh + (size_t)z * H_ * H_;
    const float* bias = (z == 0) ? bq : (z == 1) ? bk : bv;

    GemmCtx g;
    gemm_compute(g, X, W);

    if (z < 2) {
        __half* C = (z == 0) ? Cq : Ck;
#pragma unroll
        for (int mt = 0; mt < 4; ++mt) {
            int row = g.m0 + g.warp_m + mt * 16 + g.qrow;
#pragma unroll
            for (int nt = 0; nt < 4; ++nt) {
                int col = g.n0 + g.warp_n + nt * 8 + 2 * g.qcol;   // natural col
                int ncol = (col & ~15) + 4 * g.qcol + ((nt & 1) << 1);
                float b0v = __ldg(&bias[col]);
                float b1v = __ldg(&bias[col + 1]);
                uint32_t h0v = packh2(g.acc[mt * 4 + nt][0] + b0v,
                                      g.acc[mt * 4 + nt][1] + b1v);
                uint32_t h1v = packh2(g.acc[mt * 4 + nt][2] + b0v,
                                      g.acc[mt * 4 + nt][3] + b1v);
                *(uint32_t*)(C + (size_t)row * H_ + ncol)       = h0v;
                *(uint32_t*)(C + (size_t)(row + 8) * H_ + ncol) = h1v;
            }
        }
    } else {
        // V transposed: [b][h][hd][s], s pi-permuted within 16-blocks
#pragma unroll
        for (int mt = 0; mt < 4; ++mt) {
            int srow = g.m0 + g.warp_m + mt * 16 + g.qrow;
            int bb = srow >> 11, s = srow & 2047;
            int j = s & 15;                       // 0..7 here (qrow 0..7)
            int pos0 = (s & ~15) + 4 * (j >> 1) + (j & 1);   // old row j
#pragma unroll
            for (int nt = 0; nt < 4; ++nt) {
                int col = g.n0 + g.warp_n + nt * 8 + 2 * g.qcol;
                float b0v = __ldg(&bias[col]);
                float b1v = __ldg(&bias[col + 1]);
                int hh = col >> 6, hd = col & 63;
                __half* p = Cvt + ((size_t)(bb * NH_ + hh) * HD_ + hd) * S_;
                p[pos0]          = __float2half_rn(g.acc[mt * 4 + nt][0] + b0v);
                p[S_ + pos0]     = __float2half_rn(g.acc[mt * 4 + nt][1] + b1v);
                p[pos0 + 2]      = __float2half_rn(g.acc[mt * 4 + nt][2] + b0v);
                p[S_ + pos0 + 2] = __float2half_rn(g.acc[mt * 4 + nt][3] + b1v);
            }
        }
    }
}

__global__ __launch_bounds__(256, 2)
void out_gemm_kernel(const __half* __restrict__ X, const __half* __restrict__ wh,
                     const float* __restrict__ bias, float* __restrict__ C)
{
    GemmCtx g;
    gemm_compute(g, X, wh + (size_t)3 * H_ * H_);
#pragma unroll
    for (int mt = 0; mt < 4; ++mt) {
        int row = g.m0 + g.warp_m + mt * 16 + g.qrow;
#pragma unroll
        for (int nt = 0; nt < 4; ++nt) {
            int col = g.n0 + g.warp_n + nt * 8 + 2 * g.qcol;
            float b0v = __ldg(&bias[col]);
            float b1v = __ldg(&bias[col + 1]);
            *(float2*)(C + (size_t)row * H_ + col) =
                make_float2(g.acc[mt * 4 + nt][0] + b0v, g.acc[mt * 4 + nt][1] + b1v);
            *(float2*)(C + (size_t)(row + 8) * H_ + col) =
                make_float2(g.acc[mt * 4 + nt][2] + b0v, g.acc[mt * 4 + nt][3] + b1v);
        }
    }
}

// ===========================================================================
// fp16 mma flash attention (R13/R14-proven, unchanged). CTA: 128 Q rows,
// 8 warps. KV chunk 64, 3-stage cp.async, ONE barrier per chunk, occ 2.
// pi-permuted operands, RSTH=80 conflict-free LDS.64 fragments.
// exp(t) interleaved with PV(t) per 16-col kv block.
// ===========================================================================
#define KVC 64
#define NCH (S_ / KVC)          // 32
#define RSTH 80                 // smem row stride in halves (64 data + 16 pad)
#define TILE_HALVES (64 * RSTH)               // 5120
#define STG_HALVES  (2 * TILE_HALVES)         // K + Vt, one stage = 10240
#define ATT_SMEM_BYTES (3 * STG_HALVES * 2)   // 61440

__global__ __launch_bounds__(256, 2)
void attn_mma_kernel(const __half* __restrict__ Qh, const __half* __restrict__ Kh,
                     const __half* __restrict__ Vth, const __half* __restrict__ FMh,
                     __half* __restrict__ Oh)
{
    extern __shared__ __half smh[];
    const uint32_t sb = smem_u32(smh);

    const int tid  = threadIdx.x;
    const int wid  = tid >> 5;
    const int lane = tid & 31;
    const int gr   = lane >> 2;    // 0..7
    const int qc   = lane & 3;     // 0..3
    const int q0   = blockIdx.x * 128;
    const int h    = blockIdx.y;
    const int b    = blockIdx.z;
    const int wrow = wid * 16;
    const float L2E = 1.44269504f;

    const size_t base   = (size_t)b * S_ * H_ + (size_t)h * HD_;       // Q/K halves
    const size_t vtbase = (size_t)(b * NH_ + h) * HD_ * S_;            // Vt halves

    uint32_t qf[4][4];
    {
        const __half* Qr0 = Qh + base + (size_t)(q0 + wrow + gr) * H_;
        const __half* Qr1 = Qh + base + (size_t)(q0 + wrow + gr + 8) * H_;
#pragma unroll
        for (int ks = 0; ks < 4; ++ks) {
            int c = ks * 16 + 4 * qc;
            uint2 lo = *(const uint2*)(Qr0 + c);
            uint2 hi = *(const uint2*)(Qr1 + c);
            qf[ks][0] = lo.x; qf[ks][1] = hi.x;
            qf[ks][2] = lo.y; qf[ks][3] = hi.y;
        }
    }

    float oacc[8][4];
#pragma unroll
    for (int i = 0; i < 8; ++i)
#pragma unroll
        for (int j = 0; j < 4; ++j) oacc[i][j] = 0.0f;
    float m_lo = -1e30f, m_hi = -1e30f, l_lo = 0.0f, l_hi = 0.0f;   // l lane-local

    const int prow = tid >> 3;          // 0..31
    const int pch  = tid & 7;           // 0..7

    auto issue_chunk = [&](int c) {
        const uint32_t kb = sb + (uint32_t)((c % 3) * STG_HALVES) * 2;
        const uint32_t vb = kb + (uint32_t)TILE_HALVES * 2;
        const int k0 = c * KVC;
#pragma unroll
        for (int it = 0; it < 2; ++it) {
            int r = prow + it * 32;     // 0..63
            cp_async16(kb + (uint32_t)(r * RSTH + pch * 8) * 2,
                       Kh + base + (size_t)(k0 + r) * H_ + pch * 8);
            cp_async16(vb + (uint32_t)(r * RSTH + pch * 8) * 2,
                       Vth + vtbase + (size_t)r * S_ + k0 + pch * 8);
        }
        cp_commit();
    };

    issue_chunk(0);
    issue_chunk(1);

    const size_t fmbase_lo = ((size_t)b * S_ + (q0 + wrow + gr)) * S_;
    const size_t fmbase_hi = fmbase_lo + (size_t)8 * S_;

    for (int c = 0; c < NCH; ++c) {
        cp_wait<1>();
        __syncthreads();
        if (c + 2 < NCH) issue_chunk(c + 2);
        else cp_commit();

        const __half* Ks = smh + (c % 3) * STG_HALVES;
        const __half* Vs = Ks + TILE_HALVES;
        const int k0 = c * KVC;

        // ---- S = Q K^T (uint2 LDS.64 fragment loads) ----
        float sv[8][4];
#pragma unroll
        for (int i = 0; i < 8; ++i)
#pragma unroll
            for (int j = 0; j < 4; ++j) sv[i][j] = 0.0f;

#pragma unroll
        for (int ks = 0; ks < 4; ++ks) {
            const int kk = ks * 16 + 4 * qc;
#pragma unroll
            for (int nt = 0; nt < 8; ++nt) {
                uint2 bb = *(const uint2*)(Ks + (nt * 8 + gr) * RSTH + kk);
                mma_f16(sv[nt][0], sv[nt][1], sv[nt][2], sv[nt][3],
                        qf[ks][0], qf[ks][1], qf[ks][2], qf[ks][3], bb.x, bb.y);
            }
        }

        // ---- fused mask (fp16, streaming) + row max ----
        float tmax_lo = -1e30f, tmax_hi = -1e30f;
#pragma unroll
        for (int nt = 0; nt < 8; ++nt) {
            int colo = k0 + nt * 8 + 2 * qc;
            uint32_t ul = __ldcs((const uint32_t*)(FMh + fmbase_lo + colo));
            uint32_t uh = __ldcs((const uint32_t*)(FMh + fmbase_hi + colo));
            float2 fl = __half22float2(*(const __half2*)&ul);
            float2 fh = __half22float2(*(const __half2*)&uh);
            float s0 = (fl.x < 0.0f) ? -1e30f : sv[nt][0] * fl.x;
            float s1 = (fl.y < 0.0f) ? -1e30f : sv[nt][1] * fl.y;
            float s2 = (fh.x < 0.0f) ? -1e30f : sv[nt][2] * fh.x;
            float s3 = (fh.y < 0.0f) ? -1e30f : sv[nt][3] * fh.y;
            sv[nt][0] = s0; sv[nt][1] = s1; sv[nt][2] = s2; sv[nt][3] = s3;
            tmax_lo = fmaxf(tmax_lo, fmaxf(s0, s1));
            tmax_hi = fmaxf(tmax_hi, fmaxf(s2, s3));
        }
        tmax_lo = fmaxf(tmax_lo, __shfl_xor_sync(0xffffffffu, tmax_lo, 1));
        tmax_lo = fmaxf(tmax_lo, __shfl_xor_sync(0xffffffffu, tmax_lo, 2));
        tmax_hi = fmaxf(tmax_hi, __shfl_xor_sync(0xffffffffu, tmax_hi, 1));
        tmax_hi = fmaxf(tmax_hi, __shfl_xor_sync(0xffffffffu, tmax_hi, 2));

        float newm_lo = fmaxf(m_lo, tmax_lo);
        float newm_hi = fmaxf(m_hi, tmax_hi);
        float alpha_lo = __expf(m_lo - newm_lo);
        float alpha_hi = __expf(m_hi - newm_hi);
        m_lo = newm_lo; m_hi = newm_hi;

        // ---- rescale O ----
#pragma unroll
        for (int nt = 0; nt < 8; ++nt) {
            oacc[nt][0] *= alpha_lo; oacc[nt][1] *= alpha_lo;
            oacc[nt][2] *= alpha_hi; oacc[nt][3] *= alpha_hi;
        }
        l_lo *= alpha_lo;
        l_hi *= alpha_hi;

        // ---- interleaved: exp(block t) then PV(block t) ----
        const float ml_lo = newm_lo * L2E;
        const float ml_hi = newm_hi * L2E;
        float rs_lo = 0.0f, rs_hi = 0.0f;
#pragma unroll
        for (int t = 0; t < 4; ++t) {
            uint32_t a0, a1, a2, a3;
            {
                const int n0i = 2 * t;
                float t0 = fmaf(sv[n0i][0], L2E, -ml_lo);
                float t1 = fmaf(sv[n0i][1], L2E, -ml_lo);
                float t2 = fmaf(sv[n0i][2], L2E, -ml_hi);
                float t3 = fmaf(sv[n0i][3], L2E, -ml_hi);
                a0 = ex2_h2(packh2(t0, t1));
                a1 = ex2_h2(packh2(t2, t3));
                float u0 = fmaf(sv[n0i + 1][0], L2E, -ml_lo);
                float u1 = fmaf(sv[n0i + 1][1], L2E, -ml_lo);
                float u2 = fmaf(sv[n0i + 1][2], L2E, -ml_hi);
                float u3 = fmaf(sv[n0i + 1][3], L2E, -ml_hi);
                a2 = ex2_h2(packh2(u0, u1));
                a3 = ex2_h2(packh2(u2, u3));
                float2 f0 = __half22float2(*(const __half2*)&a0);
                float2 f1 = __half22float2(*(const __half2*)&a1);
                float2 f2 = __half22float2(*(const __half2*)&a2);
                float2 f3 = __half22float2(*(const __half2*)&a3);
                rs_lo += f0.x + f0.y + f2.x + f2.y;
                rs_hi += f1.x + f1.y + f3.x + f3.y;
            }
            const int kk = t * 16 + 4 * qc;
#pragma unroll
            for (int nt = 0; nt < 8; ++nt) {
                uint2 bb = *(const uint2*)(Vs + (nt * 8 + gr) * RSTH + kk);
                mma_f16(oacc[nt][0], oacc[nt][1], oacc[nt][2], oacc[nt][3],
                        a0, a1, a2, a3, bb.x, bb.y);
            }
        }
        l_lo += rs_lo;
        l_hi += rs_hi;
    }

    // ---- final l reduction + epilogue: natural-order fp16 AO ----
    l_lo += __shfl_xor_sync(0xffffffffu, l_lo, 1);
    l_lo += __shfl_xor_sync(0xffffffffu, l_lo, 2);
    l_hi += __shfl_xor_sync(0xffffffffu, l_hi, 1);
    l_hi += __shfl_xor_sync(0xffffffffu, l_hi, 2);
    float inv_lo = 1.0f / l_lo;
    float inv_hi = 1.0f / l_hi;
    __half* Or0 = Oh + base + (size_t)(q0 + wrow + gr) * H_;
    __half* Or1 = Oh + base + (size_t)(q0 + wrow + gr + 8) * H_;
#pragma unroll
    for (int nt = 0; nt < 8; ++nt) {
        int col = nt * 8 + 2 * qc;
        *(uint32_t*)(Or0 + col) = packh2(oacc[nt][0] * inv_lo, oacc[nt][1] * inv_lo);
        *(uint32_t*)(Or1 + col) = packh2(oacc[nt][2] * inv_hi, oacc[nt][3] * inv_hi);
    }
}

// ---------------------------------------------------------------------------
extern "C" void kernel_launch(void* const* d_in, const int* in_sizes, int n_in,
                              void* d_out, int out_size)
{
    const float* query = (const float*)d_in[0];
    const float* key   = (const float*)d_in[1];
    const float* value = (const float*)d_in[2];
    const int*   mask  = (const int*)d_in[3];
    const float* smask = (const float*)d_in[4];
    const float* Wq = (const float*)d_in[5];
    const float* bq = (const float*)d_in[6];
    const float* Wk = (const float*)d_in[7];
    const float* bk = (const float*)d_in[8];
    const float* Wv = (const float*)d_in[9];
    const float* bv = (const float*)d_in[10];
    const float* Wo = (const float*)d_in[11];
    const float* bo = (const float*)d_in[12];
    float* out = (float*)d_out;

    __half *ginh, *gwh, *gqh, *gkh, *gvt, *gaoh, *gfmh;
    cudaGetSymbolAddress((void**)&ginh, g_INh);
    cudaGetSymbolAddress((void**)&gwh,  g_Wh);
    cudaGetSymbolAddress((void**)&gqh,  g_Qh);
    cudaGetSymbolAddress((void**)&gkh,  g_Kh);
    cudaGetSymbolAddress((void**)&gvt,  g_Vt);
    cudaGetSymbolAddress((void**)&gaoh, g_AOh);
    cudaGetSymbolAddress((void**)&gfmh, g_FMh);

    cudaFuncSetAttribute(qkv_gemm_kernel,
                         cudaFuncAttributeMaxDynamicSharedMemorySize, G_SMEM_BYTES);
    cudaFuncSetAttribute(out_gemm_kernel,
                         cudaFuncAttributeMaxDynamicSharedMemorySize, G_SMEM_BYTES);
    cudaFuncSetAttribute(attn_mma_kernel,
                         cudaFuncAttributeMaxDynamicSharedMemorySize, ATT_SMEM_BYTES);

    // Prologue: input/weight cvt only (mask fusion rides in qkv z=3)
    prologue_kernel<<<PRO_CTAS, 256>>>(query, key, value, Wq, Wk, Wv, Wo,
                                       ginh, gwh);

    dim3 gblk(256);
    dim3 qkvgrid(H_ / 128, M_ / 128, 4);   // (8, 32, 4): z=3 fuses the mask
    qkv_gemm_kernel<<<qkvgrid, gblk, G_SMEM_BYTES>>>(
        ginh, gwh, bq, bk, bv, gqh, gkh, gvt, mask, smask, gfmh);

    dim3 agrid(S_ / 128, NH_, B_);         // (16, 16, 2)
    attn_mma_kernel<<<agrid, 256, ATT_SMEM_BYTES>>>(gqh, gkh, gvt, gfmh, gaoh);

    dim3 ogrid(H_ / 128, M_ / 128);        // (8, 32)
    out_gemm_kernel<<<ogrid, gblk, G_SMEM_BYTES>>>(gaoh, gwh, bo, out);
}

// round 17
// speedup vs baseline: 1.0734x; 1.0164x over previous
#include <cuda_runtime.h>
#include <cuda_fp16.h>
#include <cstdint>
#include <cstddef>

#define B_  2
#define S_  2048
#define H_  1024
#define NH_ 16
#define HD_ 64
#define M_  (B_ * S_)   // 4096 rows

// Scratch (allocation-free rule: __device__ globals)
// Qh/Kh: hd-dim pi-permuted within 16-blocks (old pair (2q,2q+1)->pos 4q,
// old pair (2q+8,2q+9)->pos 4q+2). Vt: s-dim pi-permuted. FMh: k-dim pi-permuted.
__device__ __align__(16) __half g_INh[(size_t)3 * M_ * H_];            // q,k,v inputs fp16
__device__ __align__(16) __half g_Wh[(size_t)4 * H_ * H_];             // Wq,Wk,Wv,Wo fp16
__device__ __align__(16) __half g_Qh[(size_t)M_ * H_];                 // [b][s][h] fp16 (hd pi)
__device__ __align__(16) __half g_Kh[(size_t)M_ * H_];                 // [b][s][h] fp16 (hd pi)
__device__ __align__(16) __half g_Vt[(size_t)B_ * NH_ * HD_ * S_];     // [b][h][hd][s] fp16 (s pi)
__device__ __align__(16) __half g_AOh[(size_t)M_ * H_];                // attn out fp16 (natural)
__device__ __align__(16) __half g_FMh[(size_t)B_ * S_ * S_];           // -1 or sm*0.125 (fp16, k pi)

// ---------------------------------------------------------------------------
__device__ __forceinline__ uint32_t packh2(float lo, float hi) {
    uint32_t d;
    asm("cvt.rn.f16x2.f32 %0, %1, %2;" : "=r"(d) : "f"(hi), "f"(lo));
    return d;
}
__device__ __forceinline__ uint32_t ex2_h2(uint32_t t) {
    uint32_t d;
    asm("ex2.approx.f16x2 %0, %1;" : "=r"(d) : "r"(t));
    return d;
}

__device__ __forceinline__ void mma_f16(float& d0, float& d1, float& d2, float& d3,
                                        uint32_t a0, uint32_t a1, uint32_t a2, uint32_t a3,
                                        uint32_t b0, uint32_t b1) {
    asm volatile(
        "mma.sync.aligned.m16n8k16.row.col.f32.f16.f16.f32 "
        "{%0,%1,%2,%3}, {%4,%5,%6,%7}, {%8,%9}, {%0,%1,%2,%3};"
        : "+f"(d0), "+f"(d1), "+f"(d2), "+f"(d3)
        : "r"(a0), "r"(a1), "r"(a2), "r"(a3), "r"(b0), "r"(b1));
}

__device__ __forceinline__ uint32_t smem_u32(const void* p) {
    uint32_t a;
    asm("{ .reg .u64 t; cvta.to.shared.u64 t, %1; cvt.u32.u64 %0, t; }"
        : "=r"(a) : "l"(p));
    return a;
}
__device__ __forceinline__ void cp_async16(uint32_t dst, const void* src) {
    asm volatile("cp.async.cg.shared.global [%0], [%1], 16;"
                 :: "r"(dst), "l"(src) : "memory");
}
__device__ __forceinline__ void cp_commit() {
    asm volatile("cp.async.commit_group;" ::: "memory");
}
template <int N>
__device__ __forceinline__ void cp_wait() {
    asm volatile("cp.async.wait_group %0;" :: "n"(N) : "memory");
}

// ===========================================================================
// Prologue: inputs->fp16, weights->fp16 (mask fusion rides in qkv z=3).
//   [0, 3*2^20)        : q/k/v cvt
//   [3*2^20, 4*2^20)   : weights cvt
// ===========================================================================
#define PRO_IN_END   (3u << 20)
#define PRO_TOTAL    (4u << 20)
#define PRO_CTAS     (PRO_TOTAL / 256)   // 16384

__global__ __launch_bounds__(256)
void prologue_kernel(const float* __restrict__ q, const float* __restrict__ k,
                     const float* __restrict__ v,
                     const float* __restrict__ wq, const float* __restrict__ wk,
                     const float* __restrict__ wv, const float* __restrict__ wo,
                     __half* __restrict__ inh, __half* __restrict__ wh)
{
    const uint32_t i = blockIdx.x * 256 + threadIdx.x;
    if (i < PRO_IN_END) {
        const uint32_t plane = i >> 20;
        const uint32_t idx   = i & ((1u << 20) - 1);
        const float* src = (plane == 0) ? q : (plane == 1) ? k : v;
        float4 f = ((const float4*)src)[idx];
        uint2 o;
        o.x = packh2(f.x, f.y);
        o.y = packh2(f.z, f.w);
        ((uint2*)inh)[((size_t)plane << 20) + idx] = o;
    } else {
        const uint32_t j   = i - PRO_IN_END;
        const uint32_t w   = j >> 18;
        const uint32_t idx = j & ((1u << 18) - 1);
        const float* src = (w == 0) ? wq : (w == 1) ? wk : (w == 2) ? wv : wo;
        float4 f = ((const float4*)src)[idx];
        uint2 o;
        o.x = packh2(f.x, f.y);
        o.y = packh2(f.z, f.w);
        ((uint2*)wh)[((size_t)w << 18) + idx] = o;
    }
}

// ===========================================================================
// fp16 GEMM core (R10-proven, unchanged): acc = X @ W^T. CTA 128x128,
// warp 64x32, K chunk 32, 3-stage cp.async, ONE barrier per chunk, RS=40.
// ===========================================================================
#define RS 40
#define G_STAGE_HALVES (2 * 128 * RS)              // A + B, one stage = 10240
#define G_SMEM_BYTES   (3 * G_STAGE_HALVES * 2)    // 61440
#define G_NCHUNK (H_ / 32)                          // 32

struct GemmCtx {
    int warp_m, warp_n, qrow, qcol, m0, n0;
    float acc[16][4];
};

__device__ __forceinline__ void gemm_compute(
    GemmCtx& g, const __half* __restrict__ X, const __half* __restrict__ W)
{
    extern __shared__ __half gsh[];
    const uint32_t sb = smem_u32(gsh);

    const int tid  = threadIdx.x;
    const int wid  = tid >> 5;
    const int lane = tid & 31;
    g.m0 = blockIdx.y * 128;
    g.n0 = blockIdx.x * 128;
    g.warp_m = (wid & 1) * 64;
    g.warp_n = (wid >> 1) * 32;
    g.qrow = lane >> 2;
    g.qcol = lane & 3;

    const int r0 = tid >> 1;            // 0..127
    const int h0 = (tid & 1) * 16;      // half-offset base in row

    const __half* Xa = X + (size_t)(g.m0 + r0) * H_ + h0;
    const __half* Wb = W + (size_t)(g.n0 + r0) * H_ + h0;
    const uint32_t da = sb + (uint32_t)(r0 * RS + h0) * 2;
    const uint32_t db = da + (uint32_t)(128 * RS) * 2;

    auto issue = [&](int c) {
        const uint32_t so = (uint32_t)((c % 3) * G_STAGE_HALVES) * 2;
        const int k0 = c * 32;
        cp_async16(da + so,      Xa + k0);
        cp_async16(da + so + 16, Xa + k0 + 8);
        cp_async16(db + so,      Wb + k0);
        cp_async16(db + so + 16, Wb + k0 + 8);
        cp_commit();
    };

#pragma unroll
    for (int i = 0; i < 16; ++i)
#pragma unroll
        for (int j = 0; j < 4; ++j) g.acc[i][j] = 0.0f;

    issue(0);
    issue(1);

    for (int c = 0; c < G_NCHUNK; ++c) {
        cp_wait<1>();
        __syncthreads();
        if (c + 2 < G_NCHUNK) issue(c + 2);
        else cp_commit();

        const __half* As = gsh + (c % 3) * G_STAGE_HALVES;
        const __half* Bs = As + 128 * RS;

#pragma unroll
        for (int ks = 0; ks < 2; ++ks) {
            const int kk = ks * 16 + 2 * g.qcol;
            uint32_t af[4][4];
            uint32_t bf[4][2];
#pragma unroll
            for (int mt = 0; mt < 4; ++mt) {
                const __half* ap = As + (g.warp_m + mt * 16 + g.qrow) * RS + kk;
                af[mt][0] = *(const uint32_t*)ap;
                af[mt][1] = *(const uint32_t*)(ap + 8 * RS);
                af[mt][2] = *(const uint32_t*)(ap + 8);
                af[mt][3] = *(const uint32_t*)(ap + 8 * RS + 8);
            }
#pragma unroll
            for (int nt = 0; nt < 4; ++nt) {
                const __half* bp = Bs + (g.warp_n + nt * 8 + g.qrow) * RS + kk;
                bf[nt][0] = *(const uint32_t*)bp;
                bf[nt][1] = *(const uint32_t*)(bp + 8);
            }
#pragma unroll
            for (int mt = 0; mt < 4; ++mt)
#pragma unroll
                for (int nt = 0; nt < 4; ++nt)
                    mma_f16(g.acc[mt * 4 + nt][0], g.acc[mt * 4 + nt][1],
                            g.acc[mt * 4 + nt][2], g.acc[mt * 4 + nt][3],
                            af[mt][0], af[mt][1], af[mt][2], af[mt][3],
                            bf[nt][0], bf[nt][1]);
        }
    }
}

// Fused Q/K/V projections + mask fusion.
// z=0/1 -> fp16 [b][s][h] pi-store (hd); z=2 -> fp16 V^T (s pi);
// z=3 -> mask fusion with k-dim pi-permutation (memory-only tail CTAs).
__global__ __launch_bounds__(256, 2)
void qkv_gemm_kernel(const __half* __restrict__ inh, const __half* __restrict__ wh,
                     const float* __restrict__ bq, const float* __restrict__ bk,
                     const float* __restrict__ bv,
                     __half* __restrict__ Cq, __half* __restrict__ Ck,
                     __half* __restrict__ Cvt,
                     const int* __restrict__ mask, const float* __restrict__ sm,
                     __half* __restrict__ fm)
{
    const int z = blockIdx.z;
    if (z == 3) {
        // fm = (mask==0) ? -1 : sm*0.125 (fp16), pi-permuted per 16-block.
        // 2^19 blocks of 16; 65536 threads x 8 iters.
        const int cta = blockIdx.y * gridDim.x + blockIdx.x;   // 0..255
        uint32_t i = cta * 256 + threadIdx.x;                  // block index
#pragma unroll
        for (int it = 0; it < 8; ++it, i += 65536) {
            const float4* s4 = (const float4*)(sm + (size_t)i * 16);
            const int4*   m4 = (const int4*)(mask + (size_t)i * 16);
            float4 s0 = s4[0], s1 = s4[1], s2 = s4[2], s3 = s4[3];
            int4   m0 = m4[0], m1 = m4[1], m2 = m4[2], m3 = m4[3];
            float o0  = (m0.x == 0) ? -1.0f : s0.x * 0.125f;
            float o1  = (m0.y == 0) ? -1.0f : s0.y * 0.125f;
            float o2  = (m0.z == 0) ? -1.0f : s0.z * 0.125f;
            float o3  = (m0.w == 0) ? -1.0f : s0.w * 0.125f;
            float o4  = (m1.x == 0) ? -1.0f : s1.x * 0.125f;
            float o5  = (m1.y == 0) ? -1.0f : s1.y * 0.125f;
            float o6  = (m1.z == 0) ? -1.0f : s1.z * 0.125f;
            float o7  = (m1.w == 0) ? -1.0f : s1.w * 0.125f;
            float o8  = (m2.x == 0) ? -1.0f : s2.x * 0.125f;
            float o9  = (m2.y == 0) ? -1.0f : s2.y * 0.125f;
            float o10 = (m2.z == 0) ? -1.0f : s2.z * 0.125f;
            float o11 = (m2.w == 0) ? -1.0f : s2.w * 0.125f;
            float o12 = (m3.x == 0) ? -1.0f : s3.x * 0.125f;
            float o13 = (m3.y == 0) ? -1.0f : s3.y * 0.125f;
            float o14 = (m3.z == 0) ? -1.0f : s3.z * 0.125f;
            float o15 = (m3.w == 0) ? -1.0f : s3.w * 0.125f;
            // pi order: 0,1,8,9, 2,3,10,11, 4,5,12,13, 6,7,14,15
            uint4 lo, hi;
            lo.x = packh2(o0,  o1);  lo.y = packh2(o8,  o9);
            lo.z = packh2(o2,  o3);  lo.w = packh2(o10, o11);
            hi.x = packh2(o4,  o5);  hi.y = packh2(o12, o13);
            hi.z = packh2(o6,  o7);  hi.w = packh2(o14, o15);
            uint4* d4 = (uint4*)(fm + (size_t)i * 16);
            d4[0] = lo;
            d4[1] = hi;
        }
        return;
    }

    const __half* X = inh + (size_t)z * M_ * H_;
    const __half* W = wh + (size_t)z * H_ * H_;
    const float* bias = (z == 0) ? bq : (z == 1) ? bk : bv;

    GemmCtx g;
    gemm_compute(g, X, W);

    if (z < 2) {
        __half* C = (z == 0) ? Cq : Ck;
#pragma unroll
        for (int mt = 0; mt < 4; ++mt) {
            int row = g.m0 + g.warp_m + mt * 16 + g.qrow;
#pragma unroll
            for (int nt = 0; nt < 4; ++nt) {
                int col = g.n0 + g.warp_n + nt * 8 + 2 * g.qcol;   // natural col
                int ncol = (col & ~15) + 4 * g.qcol + ((nt & 1) << 1);
                float b0v = __ldg(&bias[col]);
                float b1v = __ldg(&bias[col + 1]);
                uint32_t h0v = packh2(g.acc[mt * 4 + nt][0] + b0v,
                                      g.acc[mt * 4 + nt][1] + b1v);
                uint32_t h1v = packh2(g.acc[mt * 4 + nt][2] + b0v,
                                      g.acc[mt * 4 + nt][3] + b1v);
                *(uint32_t*)(C + (size_t)row * H_ + ncol)       = h0v;
                *(uint32_t*)(C + (size_t)(row + 8) * H_ + ncol) = h1v;
            }
        }
    } else {
        // V transposed: [b][h][hd][s], s pi-permuted within 16-blocks
#pragma unroll
        for (int mt = 0; mt < 4; ++mt) {
            int srow = g.m0 + g.warp_m + mt * 16 + g.qrow;
            int bb = srow >> 11, s = srow & 2047;
            int j = s & 15;                       // 0..7 here (qrow 0..7)
            int pos0 = (s & ~15) + 4 * (j >> 1) + (j & 1);   // old row j
#pragma unroll
            for (int nt = 0; nt < 4; ++nt) {
                int col = g.n0 + g.warp_n + nt * 8 + 2 * g.qcol;
                float b0v = __ldg(&bias[col]);
                float b1v = __ldg(&bias[col + 1]);
                int hh = col >> 6, hd = col & 63;
                __half* p = Cvt + ((size_t)(bb * NH_ + hh) * HD_ + hd) * S_;
                p[pos0]          = __float2half_rn(g.acc[mt * 4 + nt][0] + b0v);
                p[S_ + pos0]     = __float2half_rn(g.acc[mt * 4 + nt][1] + b1v);
                p[pos0 + 2]      = __float2half_rn(g.acc[mt * 4 + nt][2] + b0v);
                p[S_ + pos0 + 2] = __float2half_rn(g.acc[mt * 4 + nt][3] + b1v);
            }
        }
    }
}

__global__ __launch_bounds__(256, 2)
void out_gemm_kernel(const __half* __restrict__ X, const __half* __restrict__ wh,
                     const float* __restrict__ bias, float* __restrict__ C)
{
    GemmCtx g;
    gemm_compute(g, X, wh + (size_t)3 * H_ * H_);
#pragma unroll
    for (int mt = 0; mt < 4; ++mt) {
        int row = g.m0 + g.warp_m + mt * 16 + g.qrow;
#pragma unroll
        for (int nt = 0; nt < 4; ++nt) {
            int col = g.n0 + g.warp_n + nt * 8 + 2 * g.qcol;
            float b0v = __ldg(&bias[col]);
            float b1v = __ldg(&bias[col + 1]);
            *(float2*)(C + (size_t)row * H_ + col) =
                make_float2(g.acc[mt * 4 + nt][0] + b0v, g.acc[mt * 4 + nt][1] + b1v);
            *(float2*)(C + (size_t)(row + 8) * H_ + col) =
                make_float2(g.acc[mt * 4 + nt][2] + b0v, g.acc[mt * 4 + nt][3] + b1v);
        }
    }
}

// ===========================================================================
// fp16 mma flash attention. CTA: 128 Q rows, 8 warps. KV chunk 64,
// 3-stage cp.async, ONE barrier per chunk, occ 2. pi-permuted operands,
// RSTH=80 conflict-free LDS.64 fragments. exp(t) interleaved with PV(t).
// R17: FM pi-permuted -> 8 uint2 loads/chunk, hoisted before QK MMAs.
// ===========================================================================
#define KVC 64
#define NCH (S_ / KVC)          // 32
#define RSTH 80                 // smem row stride in halves (64 data + 16 pad)
#define TILE_HALVES (64 * RSTH)               // 5120
#define STG_HALVES  (2 * TILE_HALVES)         // K + Vt, one stage = 10240
#define ATT_SMEM_BYTES (3 * STG_HALVES * 2)   // 61440

__global__ __launch_bounds__(256, 2)
void attn_mma_kernel(const __half* __restrict__ Qh, const __half* __restrict__ Kh,
                     const __half* __restrict__ Vth, const __half* __restrict__ FMh,
                     __half* __restrict__ Oh)
{
    extern __shared__ __half smh[];
    const uint32_t sb = smem_u32(smh);

    const int tid  = threadIdx.x;
    const int wid  = tid >> 5;
    const int lane = tid & 31;
    const int gr   = lane >> 2;    // 0..7
    const int qc   = lane & 3;     // 0..3
    const int q0   = blockIdx.x * 128;
    const int h    = blockIdx.y;
    const int b    = blockIdx.z;
    const int wrow = wid * 16;
    const float L2E = 1.44269504f;

    const size_t base   = (size_t)b * S_ * H_ + (size_t)h * HD_;       // Q/K halves
    const size_t vtbase = (size_t)(b * NH_ + h) * HD_ * S_;            // Vt halves

    uint32_t qf[4][4];
    {
        const __half* Qr0 = Qh + base + (size_t)(q0 + wrow + gr) * H_;
        const __half* Qr1 = Qh + base + (size_t)(q0 + wrow + gr + 8) * H_;
#pragma unroll
        for (int ks = 0; ks < 4; ++ks) {
            int c = ks * 16 + 4 * qc;
            uint2 lo = *(const uint2*)(Qr0 + c);
            uint2 hi = *(const uint2*)(Qr1 + c);
            qf[ks][0] = lo.x; qf[ks][1] = hi.x;
            qf[ks][2] = lo.y; qf[ks][3] = hi.y;
        }
    }

    float oacc[8][4];
#pragma unroll
    for (int i = 0; i < 8; ++i)
#pragma unroll
        for (int j = 0; j < 4; ++j) oacc[i][j] = 0.0f;
    float m_lo = -1e30f, m_hi = -1e30f, l_lo = 0.0f, l_hi = 0.0f;   // l lane-local

    const int prow = tid >> 3;          // 0..31
    const int pch  = tid & 7;           // 0..7

    auto issue_chunk = [&](int c) {
        const uint32_t kb = sb + (uint32_t)((c % 3) * STG_HALVES) * 2;
        const uint32_t vb = kb + (uint32_t)TILE_HALVES * 2;
        const int k0 = c * KVC;
#pragma unroll
        for (int it = 0; it < 2; ++it) {
            int r = prow + it * 32;     // 0..63
            cp_async16(kb + (uint32_t)(r * RSTH + pch * 8) * 2,
                       Kh + base + (size_t)(k0 + r) * H_ + pch * 8);
            cp_async16(vb + (uint32_t)(r * RSTH + pch * 8) * 2,
                       Vth + vtbase + (size_t)r * S_ + k0 + pch * 8);
        }
        cp_commit();
    };

    issue_chunk(0);
    issue_chunk(1);

    const size_t fmbase_lo = ((size_t)b * S_ + (q0 + wrow + gr)) * S_;
    const size_t fmbase_hi = fmbase_lo + (size_t)8 * S_;

    for (int c = 0; c < NCH; ++c) {
        cp_wait<1>();
        __syncthreads();
        if (c + 2 < NCH) issue_chunk(c + 2);
        else cp_commit();

        const __half* Ks = smh + (c % 3) * STG_HALVES;
        const __half* Vs = Ks + TILE_HALVES;
        const int k0 = c * KVC;

        // ---- FM loads hoisted: latency covered by the QK MMA block ----
        uint2 fml[4], fmh[4];
#pragma unroll
        for (int t = 0; t < 4; ++t) {
            size_t off = (size_t)k0 + t * 16 + 4 * qc;
            fml[t] = __ldcs((const uint2*)(FMh + fmbase_lo + off));
            fmh[t] = __ldcs((const uint2*)(FMh + fmbase_hi + off));
        }

        // ---- S = Q K^T (uint2 LDS.64 fragment loads) ----
        float sv[8][4];
#pragma unroll
        for (int i = 0; i < 8; ++i)
#pragma unroll
            for (int j = 0; j < 4; ++j) sv[i][j] = 0.0f;

#pragma unroll
        for (int ks = 0; ks < 4; ++ks) {
            const int kk = ks * 16 + 4 * qc;
#pragma unroll
            for (int nt = 0; nt < 8; ++nt) {
                uint2 bb = *(const uint2*)(Ks + (nt * 8 + gr) * RSTH + kk);
                mma_f16(sv[nt][0], sv[nt][1], sv[nt][2], sv[nt][3],
                        qf[ks][0], qf[ks][1], qf[ks][2], qf[ks][3], bb.x, bb.y);
            }
        }

        // ---- mask (pre-loaded FM) + row max ----
        float tmax_lo = -1e30f, tmax_hi = -1e30f;
#pragma unroll
        for (int nt = 0; nt < 8; ++nt) {
            uint32_t ul = (nt & 1) ? fml[nt >> 1].y : fml[nt >> 1].x;
            uint32_t uh = (nt & 1) ? fmh[nt >> 1].y : fmh[nt >> 1].x;
            float2 fl = __half22float2(*(const __half2*)&ul);
            float2 fh = __half22float2(*(const __half2*)&uh);
            float s0 = (fl.x < 0.0f) ? -1e30f : sv[nt][0] * fl.x;
            float s1 = (fl.y < 0.0f) ? -1e30f : sv[nt][1] * fl.y;
            float s2 = (fh.x < 0.0f) ? -1e30f : sv[nt][2] * fh.x;
            float s3 = (fh.y < 0.0f) ? -1e30f : sv[nt][3] * fh.y;
            sv[nt][0] = s0; sv[nt][1] = s1; sv[nt][2] = s2; sv[nt][3] = s3;
            tmax_lo = fmaxf(tmax_lo, fmaxf(s0, s1));
            tmax_hi = fmaxf(tmax_hi, fmaxf(s2, s3));
        }
        tmax_lo = fmaxf(tmax_lo, __shfl_xor_sync(0xffffffffu, tmax_lo, 1));
        tmax_lo = fmaxf(tmax_lo, __shfl_xor_sync(0xffffffffu, tmax_lo, 2));
        tmax_hi = fmaxf(tmax_hi, __shfl_xor_sync(0xffffffffu, tmax_hi, 1));
        tmax_hi = fmaxf(tmax_hi, __shfl_xor_sync(0xffffffffu, tmax_hi, 2));

        float newm_lo = fmaxf(m_lo, tmax_lo);
        float newm_hi = fmaxf(m_hi, tmax_hi);
        float alpha_lo = __expf(m_lo - newm_lo);
        float alpha_hi = __expf(m_hi - newm_hi);
        m_lo = newm_lo; m_hi = newm_hi;

        // ---- rescale O ----
#pragma unroll
        for (int nt = 0; nt < 8; ++nt) {
            oacc[nt][0] *= alpha_lo; oacc[nt][1] *= alpha_lo;
            oacc[nt][2] *= alpha_hi; oacc[nt][3] *= alpha_hi;
        }
        l_lo *= alpha_lo;
        l_hi *= alpha_hi;

        // ---- interleaved: exp(block t) then PV(block t) ----
        const float ml_lo = newm_lo * L2E;
        const float ml_hi = newm_hi * L2E;
        float rs_lo = 0.0f, rs_hi = 0.0f;
#pragma unroll
        for (int t = 0; t < 4; ++t) {
            uint32_t a0, a1, a2, a3;
            {
                const int n0i = 2 * t;
                float t0 = fmaf(sv[n0i][0], L2E, -ml_lo);
                float t1 = fmaf(sv[n0i][1], L2E, -ml_lo);
                float t2 = fmaf(sv[n0i][2], L2E, -ml_hi);
                float t3 = fmaf(sv[n0i][3], L2E, -ml_hi);
                a0 = ex2_h2(packh2(t0, t1));
                a1 = ex2_h2(packh2(t2, t3));
                float u0 = fmaf(sv[n0i + 1][0], L2E, -ml_lo);
                float u1 = fmaf(sv[n0i + 1][1], L2E, -ml_lo);
                float u2 = fmaf(sv[n0i + 1][2], L2E, -ml_hi);
                float u3 = fmaf(sv[n0i + 1][3], L2E, -ml_hi);
                a2 = ex2_h2(packh2(u0, u1));
                a3 = ex2_h2(packh2(u2, u3));
                float2 f0 = __half22float2(*(const __half2*)&a0);
                float2 f1 = __half22float2(*(const __half2*)&a1);
                float2 f2 = __half22float2(*(const __half2*)&a2);
                float2 f3 = __half22float2(*(const __half2*)&a3);
                rs_lo += f0.x + f0.y + f2.x + f2.y;
                rs_hi += f1.x + f1.y + f3.x + f3.y;
            }
            const int kk = t * 16 + 4 * qc;
#pragma unroll
            for (int nt = 0; nt < 8; ++nt) {
                uint2 bb = *(const uint2*)(Vs + (nt * 8 + gr) * RSTH + kk);
                mma_f16(oacc[nt][0], oacc[nt][1], oacc[nt][2], oacc[nt][3],
                        a0, a1, a2, a3, bb.x, bb.y);
            }
        }
        l_lo += rs_lo;
        l_hi += rs_hi;
    }

    // ---- final l reduction + epilogue: natural-order fp16 AO ----
    l_lo += __shfl_xor_sync(0xffffffffu, l_lo, 1);
    l_lo += __shfl_xor_sync(0xffffffffu, l_lo, 2);
    l_hi += __shfl_xor_sync(0xffffffffu, l_hi, 1);
    l_hi += __shfl_xor_sync(0xffffffffu, l_hi, 2);
    float inv_lo = 1.0f / l_lo;
    float inv_hi = 1.0f / l_hi;
    __half* Or0 = Oh + base + (size_t)(q0 + wrow + gr) * H_;
    __half* Or1 = Oh + base + (size_t)(q0 + wrow + gr + 8) * H_;
#pragma unroll
    for (int nt = 0; nt < 8; ++nt) {
        int col = nt * 8 + 2 * qc;
        *(uint32_t*)(Or0 + col) = packh2(oacc[nt][0] * inv_lo, oacc[nt][1] * inv_lo);
        *(uint32_t*)(Or1 + col) = packh2(oacc[nt][2] * inv_hi, oacc[nt][3] * inv_hi);
    }
}

// ---------------------------------------------------------------------------
extern "C" void kernel_launch(void* const* d_in, const int* in_sizes, int n_in,
                              void* d_out, int out_size)
{
    const float* query = (const float*)d_in[0];
    const float* key   = (const float*)d_in[1];
    const float* value = (const float*)d_in[2];
    const int*   mask  = (const int*)d_in[3];
    const float* smask = (const float*)d_in[4];
    const float* Wq = (const float*)d_in[5];
    const float* bq = (const float*)d_in[6];
    const float* Wk = (const float*)d_in[7];
    const float* bk = (const float*)d_in[8];
    const float* Wv = (const float*)d_in[9];
    const float* bv = (const float*)d_in[10];
    const float* Wo = (const float*)d_in[11];
    const float* bo = (const float*)d_in[12];
    float* out = (float*)d_out;

    __half *ginh, *gwh, *gqh, *gkh, *gvt, *gaoh, *gfmh;
    cudaGetSymbolAddress((void**)&ginh, g_INh);
    cudaGetSymbolAddress((void**)&gwh,  g_Wh);
    cudaGetSymbolAddress((void**)&gqh,  g_Qh);
    cudaGetSymbolAddress((void**)&gkh,  g_Kh);
    cudaGetSymbolAddress((void**)&gvt,  g_Vt);
    cudaGetSymbolAddress((void**)&gaoh, g_AOh);
    cudaGetSymbolAddress((void**)&gfmh, g_FMh);

    cudaFuncSetAttribute(qkv_gemm_kernel,
                         cudaFuncAttributeMaxDynamicSharedMemorySize, G_SMEM_BYTES);
    cudaFuncSetAttribute(out_gemm_kernel,
                         cudaFuncAttributeMaxDynamicSharedMemorySize, G_SMEM_BYTES);
    cudaFuncSetAttribute(attn_mma_kernel,
                         cudaFuncAttributeMaxDynamicSharedMemorySize, ATT_SMEM_BYTES);

    // Prologue: input/weight cvt only (mask fusion rides in qkv z=3)
    prologue_kernel<<<PRO_CTAS, 256>>>(query, key, value, Wq, Wk, Wv, Wo,
                                       ginh, gwh);

    dim3 gblk(256);
    dim3 qkvgrid(H_ / 128, M_ / 128, 4);   // (8, 32, 4): z=3 fuses the mask
    qkv_gemm_kernel<<<qkvgrid, gblk, G_SMEM_BYTES>>>(
        ginh, gwh, bq, bk, bv, gqh, gkh, gvt, mask, smask, gfmh);

    dim3 agrid(S_ / 128, NH_, B_);         // (16, 16, 2)
    attn_mma_kernel<<<agrid, 256, ATT_SMEM_BYTES>>>(gqh, gkh, gvt, gfmh, gaoh);

    dim3 ogrid(H_ / 128, M_ / 128);        // (8, 32)
    out_gemm_kernel<<<ogrid, gblk, G_SMEM_BYTES>>>(gaoh, gwh, bo, out);
}